// round 10
// baseline (speedup 1.0000x reference)
#include <cuda_runtime.h>
#include <cuda_bf16.h>
#include <cstdint>

// Problem constants
#define N_NODE 40000
#define N_EDGE 320000
#define DIM    1024
#define NBLK_SCAN 40            // ceil(40000/1024)
#define DCHUNKS 4               // 4 x 256-float slices

#define GEMM_MBLKS ((N_NODE + 127) / 128)     // 313
#define GEMM_NBLKS (DIM / 128)                // 8
#define GEMM_BLOCKS (GEMM_MBLKS * GEMM_NBLKS) // 2504

// ---------------- device scratch (no cudaMalloc allowed) ----------------
__device__ int   g_deg[3 * N_NODE];
__device__ int   g_offs[3 * (N_NODE + 1)];
__device__ int   g_cursor[3 * N_NODE];
__device__ int   g_sorted_src[3 * N_EDGE];
__device__ int   g_bsum[3 * NBLK_SCAN];
__device__ float g_agg0[(size_t)N_NODE * DIM];   // dpi
__device__ float g_agg1[(size_t)N_NODE * DIM];   // ppi
__device__ float g_agg2[(size_t)N_NODE * DIM];   // ddi
__device__ float g_wt0[(size_t)DIM * DIM];
__device__ float g_wt1[(size_t)DIM * DIM];
__device__ float g_wt2[(size_t)DIM * DIM];

// ---------------- helpers ----------------
__device__ __forceinline__ uint32_t f2tf32(float x) {
    uint32_t r;
    asm("cvt.rna.tf32.f32 %0, %1;" : "=r"(r) : "f"(x));
    return r;
}

__device__ __forceinline__ uint32_t smem_to_u32(const void* smem_ptr) {
    uint32_t addr;
    asm("{ .reg .u64 tmp; cvta.to.shared.u64 tmp, %1; cvt.u32.u64 %0, tmp; }"
        : "=r"(addr) : "l"(smem_ptr));
    return addr;
}

__device__ __forceinline__ void cp_async16(uint32_t smem_addr, const void* gptr, uint32_t src_size) {
    asm volatile("cp.async.ca.shared.global [%0], [%1], 16, %2;"
                 :: "r"(smem_addr), "l"(gptr), "r"(src_size));
}
__device__ __forceinline__ void cp_async_commit() {
    asm volatile("cp.async.commit_group;" ::: "memory");
}
template <int N>
__device__ __forceinline__ void cp_async_wait() {
    asm volatile("cp.async.wait_group %0;" :: "n"(N) : "memory");
}

__device__ __forceinline__ void mma_tf32(float& c0, float& c1, float& c2, float& c3,
                                         uint32_t a0, uint32_t a1, uint32_t a2, uint32_t a3,
                                         uint32_t b0, uint32_t b1) {
    asm volatile(
        "mma.sync.aligned.m16n8k8.row.col.f32.tf32.tf32.f32 "
        "{%0,%1,%2,%3}, {%4,%5,%6,%7}, {%8,%9}, {%0,%1,%2,%3};"
        : "+f"(c0), "+f"(c1), "+f"(c2), "+f"(c3)
        : "r"(a0), "r"(a1), "r"(a2), "r"(a3), "r"(b0), "r"(b1));
}

// ---------------- sort-by-dst pipeline (per-relation scratch, rel = 0..2) ----------------
__global__ void zero_deg_kernel(int rel) {
    int i = blockIdx.x * blockDim.x + threadIdx.x;
    if (i < N_NODE) g_deg[rel * N_NODE + i] = 0;
}

__global__ void hist_kernel(int rel, const int* __restrict__ dst) {
    int i = blockIdx.x * blockDim.x + threadIdx.x;
    if (i < N_EDGE) atomicAdd(&g_deg[rel * N_NODE + dst[i]], 1);
}

__global__ void scan_block_kernel(int rel) {
    int t = threadIdx.x;
    int lane = t & 31, wid = t >> 5;
    int gidx = blockIdx.x * 1024 + t;
    int v = (gidx < N_NODE) ? g_deg[rel * N_NODE + gidx] : 0;
    int x = v;
    #pragma unroll
    for (int o = 1; o < 32; o <<= 1) {
        int y = __shfl_up_sync(0xFFFFFFFFu, x, o);
        if (lane >= o) x += y;
    }
    __shared__ int wsum[32];
    if (lane == 31) wsum[wid] = x;
    __syncthreads();
    if (wid == 0) {
        int w = wsum[lane];
        #pragma unroll
        for (int o = 1; o < 32; o <<= 1) {
            int y = __shfl_up_sync(0xFFFFFFFFu, w, o);
            if (lane >= o) w += y;
        }
        wsum[lane] = w;
    }
    __syncthreads();
    int incl = x + (wid ? wsum[wid - 1] : 0);
    if (gidx < N_NODE) g_offs[rel * (N_NODE + 1) + gidx] = incl - v;
    __syncthreads();
    if (t == 1023) g_bsum[rel * NBLK_SCAN + blockIdx.x] = wsum[31];
}

// fused: block-offset prefix computed in-block from g_bsum; writes final offs + cursor
__global__ void scan_add_kernel(int rel) {
    __shared__ int sh[NBLK_SCAN];
    int t = threadIdx.x;
    if (t < NBLK_SCAN) sh[t] = g_bsum[rel * NBLK_SCAN + t];
    __syncthreads();
    int boff = 0;
    for (int b = 0; b < blockIdx.x; ++b) boff += sh[b];   // uniform per block
    int gidx = blockIdx.x * 1024 + t;
    if (gidx < N_NODE) {
        int o = g_offs[rel * (N_NODE + 1) + gidx] + boff;
        g_offs[rel * (N_NODE + 1) + gidx] = o;
        g_cursor[rel * N_NODE + gidx] = o;
    }
    if (blockIdx.x == 0 && t == 0)
        g_offs[rel * (N_NODE + 1) + N_NODE] = N_EDGE;
}

__global__ void scatter_kernel(int rel, const int* __restrict__ src, const int* __restrict__ dst) {
    int i = blockIdx.x * blockDim.x + threadIdx.x;
    if (i < N_EDGE) {
        int pos = atomicAdd(&g_cursor[rel * N_NODE + dst[i]], 1);
        g_sorted_src[rel * N_EDGE + pos] = src[i];
    }
}

// ---------------- aggregate bodies ----------------
// chunked: 64 threads, one 256-float slice of one node
__global__ void aggregate_chunk_kernel(int rel, int dchunk,
                                       const float* __restrict__ xsrc,
                                       float* __restrict__ aggout) {
    int v = blockIdx.x;
    const int* offs = g_offs + rel * (N_NODE + 1);
    const int* srt  = g_sorted_src + rel * N_EDGE;
    int beg = offs[v];
    int end = offs[v + 1];
    int t = threadIdx.x;                       // 0..63
    const int qoff = dchunk * 64 + t;

    float4 acc = make_float4(0.f, 0.f, 0.f, 0.f);
    const float4* xs = reinterpret_cast<const float4*>(xsrc);
    int e = beg;
    for (; e + 7 < end; e += 8) {
        float4 r[8];
        #pragma unroll
        for (int j = 0; j < 8; j++)
            r[j] = xs[(size_t)srt[e + j] * (DIM / 4) + qoff];
        #pragma unroll
        for (int j = 0; j < 8; j++) {
            acc.x += r[j].x; acc.y += r[j].y; acc.z += r[j].z; acc.w += r[j].w;
        }
    }
    for (; e + 1 < end; e += 2) {
        float4 r0 = xs[(size_t)srt[e] * (DIM / 4) + qoff];
        float4 r1 = xs[(size_t)srt[e + 1] * (DIM / 4) + qoff];
        acc.x += r0.x + r1.x; acc.y += r0.y + r1.y;
        acc.z += r0.z + r1.z; acc.w += r0.w + r1.w;
    }
    if (e < end) {
        float4 r = xs[(size_t)srt[e] * (DIM / 4) + qoff];
        acc.x += r.x; acc.y += r.y; acc.z += r.z; acc.w += r.w;
    }
    int d = end - beg;
    float inv = 1.0f / (float)(d > 1 ? d : 1);
    float4 o;
    o.x = __uint_as_float(f2tf32(acc.x * inv));
    o.y = __uint_as_float(f2tf32(acc.y * inv));
    o.z = __uint_as_float(f2tf32(acc.z * inv));
    o.w = __uint_as_float(f2tf32(acc.w * inv));
    reinterpret_cast<float4*>(aggout)[(size_t)v * (DIM / 4) + qoff] = o;
}

// full-row: 256 threads, one node (used inside the union kernel)
__device__ __forceinline__ void aggregate_full_body(int rel, int v,
                                                    const float* __restrict__ xsrc,
                                                    float* __restrict__ aggout) {
    const int* offs = g_offs + rel * (N_NODE + 1);
    const int* srt  = g_sorted_src + rel * N_EDGE;
    int beg = offs[v];
    int end = offs[v + 1];
    int t = threadIdx.x;                       // 0..255 = full row in float4

    float4 acc = make_float4(0.f, 0.f, 0.f, 0.f);
    const float4* xs = reinterpret_cast<const float4*>(xsrc);
    int e = beg;
    for (; e + 3 < end; e += 4) {
        float4 r[4];
        #pragma unroll
        for (int j = 0; j < 4; j++)
            r[j] = xs[(size_t)srt[e + j] * (DIM / 4) + t];
        #pragma unroll
        for (int j = 0; j < 4; j++) {
            acc.x += r[j].x; acc.y += r[j].y; acc.z += r[j].z; acc.w += r[j].w;
        }
    }
    for (; e < end; ++e) {
        float4 r = xs[(size_t)srt[e] * (DIM / 4) + t];
        acc.x += r.x; acc.y += r.y; acc.z += r.z; acc.w += r.w;
    }
    int d = end - beg;
    float inv = 1.0f / (float)(d > 1 ? d : 1);
    float4 o;
    o.x = __uint_as_float(f2tf32(acc.x * inv));
    o.y = __uint_as_float(f2tf32(acc.y * inv));
    o.z = __uint_as_float(f2tf32(acc.z * inv));
    o.w = __uint_as_float(f2tf32(acc.w * inv));
    reinterpret_cast<float4*>(aggout)[(size_t)v * (DIM / 4) + t] = o;
}

// W[k][n] -> Wt[n][k], tf32(RNA)-rounded
__global__ void transpose_round_kernel(const float* __restrict__ W, float* __restrict__ Wt) {
    __shared__ float tile[32][33];
    int bx = blockIdx.x * 32, by = blockIdx.y * 32;
    int tx = threadIdx.x, ty = threadIdx.y;   // 32 x 8
    #pragma unroll
    for (int i = 0; i < 32; i += 8)
        tile[ty + i][tx] = W[(size_t)(by + ty + i) * DIM + bx + tx];
    __syncthreads();
    #pragma unroll
    for (int i = 0; i < 32; i += 8)
        Wt[(size_t)(bx + ty + i) * DIM + by + tx] = __uint_as_float(f2tf32(tile[tx][ty + i]));
}

// ---------------- cp.async-pipelined TF32 mma.sync GEMM body ----------------
#define LDR   20
#define ATILE (128 * LDR)
#define STAGE_FLOATS (2 * ATILE)
#define NSTAGE 3
#define GEMM_SMEM_DYN (NSTAGE * STAGE_FLOATS * 4)   // 61440 B

template <int CHUNKS>
__device__ __forceinline__ void gemm_body(
    int bm, int bn,
    const float* __restrict__ A0, const float* __restrict__ A1,
    const float* __restrict__ Wt0, const float* __restrict__ Wt1,
    const float* __restrict__ bias0, const float* __restrict__ bias1,
    float* __restrict__ C, int M, float* smem)
{
    const uint32_t smem_u32 = smem_to_u32(smem);

    const int t      = threadIdx.x;
    const int lane   = t & 31;
    const int warp   = t >> 5;
    const int warp_m = warp >> 2;
    const int warp_n = warp & 3;
    const int g      = lane >> 2;
    const int tid4   = lane & 3;

    const int KT = 64 * CHUNKS;

    const int s_row0 = t >> 2;
    const int s_row1 = (t + 256) >> 2;
    const int s_c    = t & 3;

    auto stage = [&](int kt, int buf) {
        const float* Asrc = (CHUNKS == 2 && kt >= 64) ? A1 : A0;
        const float* Wsrc = (CHUNKS == 2 && kt >= 64) ? Wt1 : Wt0;
        const int k0 = (kt & 63) * 16;
        const uint32_t abase = smem_u32 + (uint32_t)buf * (STAGE_FLOATS * 4);
        const uint32_t bbase = abase + ATILE * 4;
        #pragma unroll
        for (int i = 0; i < 2; i++) {
            int row = i ? s_row1 : s_row0;
            int gm = bm + row;
            int gmc = (gm < M) ? gm : 0;
            cp_async16(abase + (uint32_t)(row * LDR + s_c * 4) * 4,
                       Asrc + (size_t)gmc * DIM + k0 + s_c * 4,
                       (gm < M) ? 16u : 0u);
            int gn = bn + row;
            cp_async16(bbase + (uint32_t)(row * LDR + s_c * 4) * 4,
                       Wsrc + (size_t)gn * DIM + k0 + s_c * 4, 16u);
        }
    };

    float c[4][4][4];
    #pragma unroll
    for (int mt = 0; mt < 4; mt++)
        #pragma unroll
        for (int nt = 0; nt < 4; nt++)
            #pragma unroll
            for (int r = 0; r < 4; r++) c[mt][nt][r] = 0.f;

    auto compute = [&](int buf) {
        const uint32_t* As = reinterpret_cast<const uint32_t*>(smem) + buf * STAGE_FLOATS;
        const uint32_t* Bs = As + ATILE;
        #pragma unroll
        for (int ks = 0; ks < 2; ks++) {
            const int kb = ks * 8;
            uint32_t a[4][4], b[4][2];
            #pragma unroll
            for (int mt = 0; mt < 4; mt++) {
                const uint32_t* ar0 = As + (warp_m * 64 + mt * 16 + g) * LDR + kb + tid4;
                const uint32_t* ar1 = ar0 + 8 * LDR;
                a[mt][0] = ar0[0]; a[mt][1] = ar1[0];
                a[mt][2] = ar0[4]; a[mt][3] = ar1[4];
            }
            #pragma unroll
            for (int nt = 0; nt < 4; nt++) {
                const uint32_t* br = Bs + (warp_n * 32 + nt * 8 + g) * LDR + kb + tid4;
                b[nt][0] = br[0]; b[nt][1] = br[4];
            }
            #pragma unroll
            for (int mt = 0; mt < 4; mt++)
                #pragma unroll
                for (int nt = 0; nt < 4; nt++)
                    mma_tf32(c[mt][nt][0], c[mt][nt][1], c[mt][nt][2], c[mt][nt][3],
                             a[mt][0], a[mt][1], a[mt][2], a[mt][3],
                             b[nt][0], b[nt][1]);
        }
    };

    stage(0, 0); cp_async_commit();
    stage(1, 1); cp_async_commit();

    int buf = 0;
    for (int kt = 0; kt < KT; ++kt) {
        cp_async_wait<1>();
        __syncthreads();
        compute(buf);
        if (kt + 2 < KT) stage(kt + 2, (buf + 2) % NSTAGE);
        cp_async_commit();
        buf = (buf + 1) % NSTAGE;
    }

    #pragma unroll
    for (int mt = 0; mt < 4; mt++) {
        int r0 = bm + warp_m * 64 + mt * 16 + g;
        int r1 = r0 + 8;
        #pragma unroll
        for (int nt = 0; nt < 4; nt++) {
            int col = bn + warp_n * 32 + nt * 8 + tid4 * 2;
            float bv0 = bias0[col], bv1 = bias0[col + 1];
            if (CHUNKS == 2) { bv0 += bias1[col]; bv1 += bias1[col + 1]; }
            if (r0 < M) {
                float* p = &C[(size_t)r0 * DIM + col];
                p[0] = c[mt][nt][0] + bv0; p[1] = c[mt][nt][1] + bv1;
            }
            if (r1 < M) {
                float* p = &C[(size_t)r1 * DIM + col];
                p[0] = c[mt][nt][2] + bv0; p[1] = c[mt][nt][3] + bv1;
            }
        }
    }
}

// plain GEMM kernel (2D grid) for the final ddi GEMM
template <int CHUNKS>
__global__ __launch_bounds__(256, 2) void gemm_tf32_cpasync(
    const float* __restrict__ A0, const float* __restrict__ A1,
    const float* __restrict__ Wt0, const float* __restrict__ Wt1,
    const float* __restrict__ bias0, const float* __restrict__ bias1,
    float* __restrict__ C, int M)
{
    extern __shared__ float smem[];
    gemm_body<CHUNKS>(blockIdx.y * 128, blockIdx.x * 128,
                      A0, A1, Wt0, Wt1, bias0, bias1, C, M, smem);
}

// ---------------- union kernel: prot GEMM (K=2048) + ddi aggregation ----------------
__global__ __launch_bounds__(256, 2) void union_gemm_agg_kernel(
    const float* __restrict__ A0, const float* __restrict__ A1,
    const float* __restrict__ Wt0, const float* __restrict__ Wt1,
    const float* __restrict__ bias0, const float* __restrict__ bias1,
    float* __restrict__ C, int M,
    int agg_rel, const float* __restrict__ xsrc, float* __restrict__ aggout)
{
    extern __shared__ float smem[];
    if (blockIdx.x < GEMM_BLOCKS) {
        int bm = (blockIdx.x / GEMM_NBLKS) * 128;
        int bn = (blockIdx.x % GEMM_NBLKS) * 128;
        gemm_body<2>(bm, bn, A0, A1, Wt0, Wt1, bias0, bias1, C, M, smem);
    } else {
        aggregate_full_body(agg_rel, blockIdx.x - GEMM_BLOCKS, xsrc, aggout);
    }
}

// ---------------- launch (single capture stream) ----------------
static void run_sort(int rel, const int* src, const int* dst)
{
    zero_deg_kernel<<<(N_NODE + 255) / 256, 256>>>(rel);
    hist_kernel<<<(N_EDGE + 255) / 256, 256>>>(rel, dst);
    scan_block_kernel<<<NBLK_SCAN, 1024>>>(rel);
    scan_add_kernel<<<NBLK_SCAN, 1024>>>(rel);
    scatter_kernel<<<(N_EDGE + 255) / 256, 256>>>(rel, src, dst);
}

extern "C" void kernel_launch(void* const* d_in, const int* in_sizes, int n_in,
                              void* d_out, int out_size)
{
    const float* x_drug = (const float*)d_in[0];
    const float* x_prot = (const float*)d_in[1];
    const float* W_ddi  = (const float*)d_in[2];
    const float* b_ddi  = (const float*)d_in[3];
    const float* W_dpi  = (const float*)d_in[4];
    const float* b_dpi  = (const float*)d_in[5];
    const float* W_ppi  = (const float*)d_in[6];
    const float* b_ppi  = (const float*)d_in[7];
    const int* src_ddi  = (const int*)d_in[8];
    const int* dst_ddi  = (const int*)d_in[9];
    const int* src_dpi  = (const int*)d_in[10];
    const int* dst_dpi  = (const int*)d_in[11];
    const int* src_ppi  = (const int*)d_in[12];
    const int* dst_ppi  = (const int*)d_in[13];

    float* out_drug = (float*)d_out;
    float* out_prot = out_drug + (size_t)N_NODE * DIM;

    float* agg0; cudaGetSymbolAddress((void**)&agg0, g_agg0);   // dpi
    float* agg1; cudaGetSymbolAddress((void**)&agg1, g_agg1);   // ppi
    float* agg2; cudaGetSymbolAddress((void**)&agg2, g_agg2);   // ddi
    float* wt0;  cudaGetSymbolAddress((void**)&wt0,  g_wt0);
    float* wt1;  cudaGetSymbolAddress((void**)&wt1,  g_wt1);
    float* wt2;  cudaGetSymbolAddress((void**)&wt2,  g_wt2);

    cudaFuncSetAttribute(gemm_tf32_cpasync<1>,
                         cudaFuncAttributeMaxDynamicSharedMemorySize, GEMM_SMEM_DYN);
    cudaFuncSetAttribute(union_gemm_agg_kernel,
                         cudaFuncAttributeMaxDynamicSharedMemorySize, GEMM_SMEM_DYN);

    dim3 tgrid(32, 32), tblk(32, 8);
    dim3 grid(GEMM_NBLKS, GEMM_MBLKS);

    // ---- all sorts up front ----
    run_sort(0, src_dpi, dst_dpi);
    run_sort(1, src_ppi, dst_ppi);
    run_sort(2, src_ddi, dst_ddi);

    // ---- weight transposes ----
    transpose_round_kernel<<<tgrid, tblk>>>(W_dpi, wt0);
    transpose_round_kernel<<<tgrid, tblk>>>(W_ppi, wt1);
    transpose_round_kernel<<<tgrid, tblk>>>(W_ddi, wt2);

    // ---- dpi + ppi aggregates (L2-chunked) ----
    for (int c = 0; c < DCHUNKS; ++c) {
        aggregate_chunk_kernel<<<N_NODE, 64>>>(0, c, x_drug, agg0);
        aggregate_chunk_kernel<<<N_NODE, 64>>>(1, c, x_prot, agg1);
    }

    // ---- union: prot GEMM (K=2048, dpi+ppi) overlapped with ddi aggregation ----
    union_gemm_agg_kernel<<<GEMM_BLOCKS + N_NODE, 256, GEMM_SMEM_DYN>>>(
        agg0, agg1, wt0, wt1, b_dpi, b_ppi, out_prot, N_NODE,
        2, x_drug, agg2);

    // ---- ddi GEMM ----
    gemm_tf32_cpasync<1><<<grid, 256, GEMM_SMEM_DYN>>>(
        agg2, nullptr, wt2, nullptr, b_ddi, nullptr, out_drug, N_NODE);
}

// round 11
// speedup vs baseline: 1.0994x; 1.0994x over previous
#include <cuda_runtime.h>
#include <cuda_bf16.h>
#include <cstdint>

// Problem constants
#define N_NODE 40000
#define N_EDGE 320000
#define DIM    1024
#define NBLK_SCAN 40            // ceil(40000/1024)
#define DCHUNKS 4               // 4 x 256-float slices

#define GEMM_MBLKS ((N_NODE + 127) / 128)     // 313
#define GEMM_NBLKS (DIM / 128)                // 8
#define GEMM_BLOCKS (GEMM_MBLKS * GEMM_NBLKS) // 2504

// ---------------- device scratch (no cudaMalloc allowed) ----------------
__device__ int   g_deg[3 * N_NODE];
__device__ int   g_offs[3 * (N_NODE + 1)];
__device__ int   g_cursor[3 * N_NODE];
__device__ int   g_sorted_src[3 * N_EDGE];
__device__ int   g_bsum[3 * NBLK_SCAN];
__device__ float g_agg0[(size_t)N_NODE * DIM];   // dpi
__device__ float g_agg1[(size_t)N_NODE * DIM];   // ppi
__device__ float g_agg2[(size_t)N_NODE * DIM];   // ddi
__device__ float g_wt0[(size_t)DIM * DIM];
__device__ float g_wt1[(size_t)DIM * DIM];
__device__ float g_wt2[(size_t)DIM * DIM];

// ---------------- helpers ----------------
__device__ __forceinline__ uint32_t f2tf32(float x) {
    uint32_t r;
    asm("cvt.rna.tf32.f32 %0, %1;" : "=r"(r) : "f"(x));
    return r;
}

__device__ __forceinline__ uint32_t smem_to_u32(const void* smem_ptr) {
    uint32_t addr;
    asm("{ .reg .u64 tmp; cvta.to.shared.u64 tmp, %1; cvt.u32.u64 %0, tmp; }"
        : "=r"(addr) : "l"(smem_ptr));
    return addr;
}

__device__ __forceinline__ void cp_async16(uint32_t smem_addr, const void* gptr, uint32_t src_size) {
    asm volatile("cp.async.ca.shared.global [%0], [%1], 16, %2;"
                 :: "r"(smem_addr), "l"(gptr), "r"(src_size));
}
__device__ __forceinline__ void cp_async_commit() {
    asm volatile("cp.async.commit_group;" ::: "memory");
}
template <int N>
__device__ __forceinline__ void cp_async_wait() {
    asm volatile("cp.async.wait_group %0;" :: "n"(N) : "memory");
}

__device__ __forceinline__ void mma_tf32(float& c0, float& c1, float& c2, float& c3,
                                         uint32_t a0, uint32_t a1, uint32_t a2, uint32_t a3,
                                         uint32_t b0, uint32_t b1) {
    asm volatile(
        "mma.sync.aligned.m16n8k8.row.col.f32.tf32.tf32.f32 "
        "{%0,%1,%2,%3}, {%4,%5,%6,%7}, {%8,%9}, {%0,%1,%2,%3};"
        : "+f"(c0), "+f"(c1), "+f"(c2), "+f"(c3)
        : "r"(a0), "r"(a1), "r"(a2), "r"(a3), "r"(b0), "r"(b1));
}

// ---------------- sort-by-dst pipeline (per-relation scratch, rel = 0..2) ----------------
__global__ void zero_deg_kernel(int rel) {
    int i = blockIdx.x * blockDim.x + threadIdx.x;
    if (i < N_NODE) g_deg[rel * N_NODE + i] = 0;
}

__global__ void hist_kernel(int rel, const int* __restrict__ dst) {
    int i = blockIdx.x * blockDim.x + threadIdx.x;
    if (i < N_EDGE) atomicAdd(&g_deg[rel * N_NODE + dst[i]], 1);
}

__global__ void scan_block_kernel(int rel) {
    int t = threadIdx.x;
    int lane = t & 31, wid = t >> 5;
    int gidx = blockIdx.x * 1024 + t;
    int v = (gidx < N_NODE) ? g_deg[rel * N_NODE + gidx] : 0;
    int x = v;
    #pragma unroll
    for (int o = 1; o < 32; o <<= 1) {
        int y = __shfl_up_sync(0xFFFFFFFFu, x, o);
        if (lane >= o) x += y;
    }
    __shared__ int wsum[32];
    if (lane == 31) wsum[wid] = x;
    __syncthreads();
    if (wid == 0) {
        int w = wsum[lane];
        #pragma unroll
        for (int o = 1; o < 32; o <<= 1) {
            int y = __shfl_up_sync(0xFFFFFFFFu, w, o);
            if (lane >= o) w += y;
        }
        wsum[lane] = w;
    }
    __syncthreads();
    int incl = x + (wid ? wsum[wid - 1] : 0);
    if (gidx < N_NODE) g_offs[rel * (N_NODE + 1) + gidx] = incl - v;
    __syncthreads();
    if (t == 1023) g_bsum[rel * NBLK_SCAN + blockIdx.x] = wsum[31];
}

// fused: block-offset prefix computed in-block from g_bsum; writes final offs + cursor
__global__ void scan_add_kernel(int rel) {
    __shared__ int sh[NBLK_SCAN];
    int t = threadIdx.x;
    if (t < NBLK_SCAN) sh[t] = g_bsum[rel * NBLK_SCAN + t];
    __syncthreads();
    int boff = 0;
    for (int b = 0; b < blockIdx.x; ++b) boff += sh[b];   // uniform per block
    int gidx = blockIdx.x * 1024 + t;
    if (gidx < N_NODE) {
        int o = g_offs[rel * (N_NODE + 1) + gidx] + boff;
        g_offs[rel * (N_NODE + 1) + gidx] = o;
        g_cursor[rel * N_NODE + gidx] = o;
    }
    if (blockIdx.x == 0 && t == 0)
        g_offs[rel * (N_NODE + 1) + N_NODE] = N_EDGE;
}

__global__ void scatter_kernel(int rel, const int* __restrict__ src, const int* __restrict__ dst) {
    int i = blockIdx.x * blockDim.x + threadIdx.x;
    if (i < N_EDGE) {
        int pos = atomicAdd(&g_cursor[rel * N_NODE + dst[i]], 1);
        g_sorted_src[rel * N_EDGE + pos] = src[i];
    }
}

// ---------------- aggregate: 64 threads, one 256-float slice of one node ----------------
__global__ void aggregate_chunk_kernel(int rel, int dchunk,
                                       const float* __restrict__ xsrc,
                                       float* __restrict__ aggout) {
    int v = blockIdx.x;
    const int* offs = g_offs + rel * (N_NODE + 1);
    const int* srt  = g_sorted_src + rel * N_EDGE;
    int beg = offs[v];
    int end = offs[v + 1];
    int t = threadIdx.x;                       // 0..63
    const int qoff = dchunk * 64 + t;

    float4 acc = make_float4(0.f, 0.f, 0.f, 0.f);
    const float4* xs = reinterpret_cast<const float4*>(xsrc);
    int e = beg;
    for (; e + 7 < end; e += 8) {
        float4 r[8];
        #pragma unroll
        for (int j = 0; j < 8; j++)
            r[j] = xs[(size_t)srt[e + j] * (DIM / 4) + qoff];
        #pragma unroll
        for (int j = 0; j < 8; j++) {
            acc.x += r[j].x; acc.y += r[j].y; acc.z += r[j].z; acc.w += r[j].w;
        }
    }
    for (; e + 1 < end; e += 2) {
        float4 r0 = xs[(size_t)srt[e] * (DIM / 4) + qoff];
        float4 r1 = xs[(size_t)srt[e + 1] * (DIM / 4) + qoff];
        acc.x += r0.x + r1.x; acc.y += r0.y + r1.y;
        acc.z += r0.z + r1.z; acc.w += r0.w + r1.w;
    }
    if (e < end) {
        float4 r = xs[(size_t)srt[e] * (DIM / 4) + qoff];
        acc.x += r.x; acc.y += r.y; acc.z += r.z; acc.w += r.w;
    }
    int d = end - beg;
    float inv = 1.0f / (float)(d > 1 ? d : 1);
    float4 o;
    o.x = __uint_as_float(f2tf32(acc.x * inv));
    o.y = __uint_as_float(f2tf32(acc.y * inv));
    o.z = __uint_as_float(f2tf32(acc.z * inv));
    o.w = __uint_as_float(f2tf32(acc.w * inv));
    reinterpret_cast<float4*>(aggout)[(size_t)v * (DIM / 4) + qoff] = o;
}

// W[k][n] -> Wt[n][k], tf32(RNA)-rounded
__global__ void transpose_round_kernel(const float* __restrict__ W, float* __restrict__ Wt) {
    __shared__ float tile[32][33];
    int bx = blockIdx.x * 32, by = blockIdx.y * 32;
    int tx = threadIdx.x, ty = threadIdx.y;   // 32 x 8
    #pragma unroll
    for (int i = 0; i < 32; i += 8)
        tile[ty + i][tx] = W[(size_t)(by + ty + i) * DIM + bx + tx];
    __syncthreads();
    #pragma unroll
    for (int i = 0; i < 32; i += 8)
        Wt[(size_t)(bx + ty + i) * DIM + by + tx] = __uint_as_float(f2tf32(tile[tx][ty + i]));
}

// ---------------- cp.async-pipelined TF32 mma.sync GEMM body ----------------
#define LDR   20
#define ATILE (128 * LDR)
#define STAGE_FLOATS (2 * ATILE)
#define NSTAGE 3
#define GEMM_SMEM_DYN (NSTAGE * STAGE_FLOATS * 4)   // 61440 B

template <int CHUNKS>
__device__ __forceinline__ void gemm_body(
    int bm, int bn,
    const float* __restrict__ A0, const float* __restrict__ A1,
    const float* __restrict__ Wt0, const float* __restrict__ Wt1,
    const float* __restrict__ bias0, const float* __restrict__ bias1,
    float* __restrict__ C, int M, float* smem)
{
    const uint32_t smem_u32 = smem_to_u32(smem);

    const int t      = threadIdx.x;
    const int lane   = t & 31;
    const int warp   = t >> 5;
    const int warp_m = warp >> 2;
    const int warp_n = warp & 3;
    const int g      = lane >> 2;
    const int tid4   = lane & 3;

    const int KT = 64 * CHUNKS;

    const int s_row0 = t >> 2;
    const int s_row1 = (t + 256) >> 2;
    const int s_c    = t & 3;

    auto stage = [&](int kt, int buf) {
        const float* Asrc = (CHUNKS == 2 && kt >= 64) ? A1 : A0;
        const float* Wsrc = (CHUNKS == 2 && kt >= 64) ? Wt1 : Wt0;
        const int k0 = (kt & 63) * 16;
        const uint32_t abase = smem_u32 + (uint32_t)buf * (STAGE_FLOATS * 4);
        const uint32_t bbase = abase + ATILE * 4;
        #pragma unroll
        for (int i = 0; i < 2; i++) {
            int row = i ? s_row1 : s_row0;
            int gm = bm + row;
            int gmc = (gm < M) ? gm : 0;
            cp_async16(abase + (uint32_t)(row * LDR + s_c * 4) * 4,
                       Asrc + (size_t)gmc * DIM + k0 + s_c * 4,
                       (gm < M) ? 16u : 0u);
            int gn = bn + row;
            cp_async16(bbase + (uint32_t)(row * LDR + s_c * 4) * 4,
                       Wsrc + (size_t)gn * DIM + k0 + s_c * 4, 16u);
        }
    };

    float c[4][4][4];
    #pragma unroll
    for (int mt = 0; mt < 4; mt++)
        #pragma unroll
        for (int nt = 0; nt < 4; nt++)
            #pragma unroll
            for (int r = 0; r < 4; r++) c[mt][nt][r] = 0.f;

    auto compute = [&](int buf) {
        const uint32_t* As = reinterpret_cast<const uint32_t*>(smem) + buf * STAGE_FLOATS;
        const uint32_t* Bs = As + ATILE;
        #pragma unroll
        for (int ks = 0; ks < 2; ks++) {
            const int kb = ks * 8;
            uint32_t a[4][4], b[4][2];
            #pragma unroll
            for (int mt = 0; mt < 4; mt++) {
                const uint32_t* ar0 = As + (warp_m * 64 + mt * 16 + g) * LDR + kb + tid4;
                const uint32_t* ar1 = ar0 + 8 * LDR;
                a[mt][0] = ar0[0]; a[mt][1] = ar1[0];
                a[mt][2] = ar0[4]; a[mt][3] = ar1[4];
            }
            #pragma unroll
            for (int nt = 0; nt < 4; nt++) {
                const uint32_t* br = Bs + (warp_n * 32 + nt * 8 + g) * LDR + kb + tid4;
                b[nt][0] = br[0]; b[nt][1] = br[4];
            }
            #pragma unroll
            for (int mt = 0; mt < 4; mt++)
                #pragma unroll
                for (int nt = 0; nt < 4; nt++)
                    mma_tf32(c[mt][nt][0], c[mt][nt][1], c[mt][nt][2], c[mt][nt][3],
                             a[mt][0], a[mt][1], a[mt][2], a[mt][3],
                             b[nt][0], b[nt][1]);
        }
    };

    stage(0, 0); cp_async_commit();
    stage(1, 1); cp_async_commit();

    int buf = 0;
    for (int kt = 0; kt < KT; ++kt) {
        cp_async_wait<1>();
        __syncthreads();
        compute(buf);
        if (kt + 2 < KT) stage(kt + 2, (buf + 2) % NSTAGE);
        cp_async_commit();
        buf = (buf + 1) % NSTAGE;
    }

    #pragma unroll
    for (int mt = 0; mt < 4; mt++) {
        int r0 = bm + warp_m * 64 + mt * 16 + g;
        int r1 = r0 + 8;
        #pragma unroll
        for (int nt = 0; nt < 4; nt++) {
            int col = bn + warp_n * 32 + nt * 8 + tid4 * 2;
            float bv0 = bias0[col], bv1 = bias0[col + 1];
            if (CHUNKS == 2) { bv0 += bias1[col]; bv1 += bias1[col + 1]; }
            if (r0 < M) {
                float* p = &C[(size_t)r0 * DIM + col];
                p[0] = c[mt][nt][0] + bv0; p[1] = c[mt][nt][1] + bv1;
            }
            if (r1 < M) {
                float* p = &C[(size_t)r1 * DIM + col];
                p[0] = c[mt][nt][2] + bv0; p[1] = c[mt][nt][3] + bv1;
            }
        }
    }
}

// combined GEMM launch: blocks [0, GEMM_BLOCKS) = prot (K=2048, dpi+ppi);
// blocks [GEMM_BLOCKS, 2*GEMM_BLOCKS) = ddi (K=1024). Short ddi CTAs backfill
// the long prot CTAs' tail wave.
__global__ __launch_bounds__(256, 2) void gemm_combined_kernel(
    const float* __restrict__ A0, const float* __restrict__ A1,
    const float* __restrict__ Wt0, const float* __restrict__ Wt1,
    const float* __restrict__ bias0, const float* __restrict__ bias1,
    float* __restrict__ Cprot,
    const float* __restrict__ A2, const float* __restrict__ Wt2,
    const float* __restrict__ bias2, float* __restrict__ Cdrug, int M)
{
    extern __shared__ float smem[];
    if (blockIdx.x < GEMM_BLOCKS) {
        int bm = (blockIdx.x / GEMM_NBLKS) * 128;
        int bn = (blockIdx.x % GEMM_NBLKS) * 128;
        gemm_body<2>(bm, bn, A0, A1, Wt0, Wt1, bias0, bias1, Cprot, M, smem);
    } else {
        int b = blockIdx.x - GEMM_BLOCKS;
        int bm = (b / GEMM_NBLKS) * 128;
        int bn = (b % GEMM_NBLKS) * 128;
        gemm_body<1>(bm, bn, A2, nullptr, Wt2, nullptr, bias2, nullptr, Cdrug, M, smem);
    }
}

// ---------------- launch (single capture stream) ----------------
static void run_sort(int rel, const int* src, const int* dst)
{
    zero_deg_kernel<<<(N_NODE + 255) / 256, 256>>>(rel);
    hist_kernel<<<(N_EDGE + 255) / 256, 256>>>(rel, dst);
    scan_block_kernel<<<NBLK_SCAN, 1024>>>(rel);
    scan_add_kernel<<<NBLK_SCAN, 1024>>>(rel);
    scatter_kernel<<<(N_EDGE + 255) / 256, 256>>>(rel, src, dst);
}

extern "C" void kernel_launch(void* const* d_in, const int* in_sizes, int n_in,
                              void* d_out, int out_size)
{
    const float* x_drug = (const float*)d_in[0];
    const float* x_prot = (const float*)d_in[1];
    const float* W_ddi  = (const float*)d_in[2];
    const float* b_ddi  = (const float*)d_in[3];
    const float* W_dpi  = (const float*)d_in[4];
    const float* b_dpi  = (const float*)d_in[5];
    const float* W_ppi  = (const float*)d_in[6];
    const float* b_ppi  = (const float*)d_in[7];
    const int* src_ddi  = (const int*)d_in[8];
    const int* dst_ddi  = (const int*)d_in[9];
    const int* src_dpi  = (const int*)d_in[10];
    const int* dst_dpi  = (const int*)d_in[11];
    const int* src_ppi  = (const int*)d_in[12];
    const int* dst_ppi  = (const int*)d_in[13];

    float* out_drug = (float*)d_out;
    float* out_prot = out_drug + (size_t)N_NODE * DIM;

    float* agg0; cudaGetSymbolAddress((void**)&agg0, g_agg0);   // dpi
    float* agg1; cudaGetSymbolAddress((void**)&agg1, g_agg1);   // ppi
    float* agg2; cudaGetSymbolAddress((void**)&agg2, g_agg2);   // ddi
    float* wt0;  cudaGetSymbolAddress((void**)&wt0,  g_wt0);
    float* wt1;  cudaGetSymbolAddress((void**)&wt1,  g_wt1);
    float* wt2;  cudaGetSymbolAddress((void**)&wt2,  g_wt2);

    cudaFuncSetAttribute(gemm_combined_kernel,
                         cudaFuncAttributeMaxDynamicSharedMemorySize, GEMM_SMEM_DYN);

    dim3 tgrid(32, 32), tblk(32, 8);

    // ---- all sorts up front ----
    run_sort(0, src_dpi, dst_dpi);
    run_sort(1, src_ppi, dst_ppi);
    run_sort(2, src_ddi, dst_ddi);

    // ---- weight transposes ----
    transpose_round_kernel<<<tgrid, tblk>>>(W_dpi, wt0);
    transpose_round_kernel<<<tgrid, tblk>>>(W_ppi, wt1);
    transpose_round_kernel<<<tgrid, tblk>>>(W_ddi, wt2);

    // ---- aggregates: interleave dpi+ddi (both gather x_drug -> shared L2 slice),
    //      then ppi (x_prot) alone ----
    for (int c = 0; c < DCHUNKS; ++c) {
        aggregate_chunk_kernel<<<N_NODE, 64>>>(0, c, x_drug, agg0);
        aggregate_chunk_kernel<<<N_NODE, 64>>>(2, c, x_drug, agg2);
    }
    for (int c = 0; c < DCHUNKS; ++c)
        aggregate_chunk_kernel<<<N_NODE, 64>>>(1, c, x_prot, agg1);

    // ---- single combined GEMM launch: prot (K=2048) + ddi (K=1024) ----
    gemm_combined_kernel<<<2 * GEMM_BLOCKS, 256, GEMM_SMEM_DYN>>>(
        agg0, agg1, wt0, wt1, b_dpi, b_ppi, out_prot,
        agg2, wt2, b_ddi, out_drug, N_NODE);
}

// round 12
// speedup vs baseline: 1.1050x; 1.0050x over previous
#include <cuda_runtime.h>
#include <cuda_bf16.h>
#include <cstdint>

// Problem constants
#define N_NODE 40000
#define N_EDGE 320000
#define DIM    1024
#define NBLK_SCAN 40            // ceil(40000/1024)
#define DCHUNKS 4               // 4 x 256-float slices

#define GEMM_MBLKS ((N_NODE + 127) / 128)     // 313
#define GEMM_NBLKS (DIM / 128)                // 8
#define GEMM_BLOCKS (GEMM_MBLKS * GEMM_NBLKS) // 2504

// ---------------- device scratch (no cudaMalloc allowed) ----------------
__device__ int   g_deg[3 * N_NODE];
__device__ int   g_offs[3 * (N_NODE + 1)];
__device__ int   g_cursor[3 * N_NODE];
__device__ int   g_sorted_src[3 * N_EDGE];
__device__ int   g_bsum[3 * NBLK_SCAN];
__device__ float g_agg0[(size_t)N_NODE * DIM];   // dpi
__device__ float g_agg1[(size_t)N_NODE * DIM];   // ppi
__device__ float g_agg2[(size_t)N_NODE * DIM];   // ddi
__device__ float g_wt0[(size_t)DIM * DIM];
__device__ float g_wt1[(size_t)DIM * DIM];
__device__ float g_wt2[(size_t)DIM * DIM];

// ---------------- helpers ----------------
__device__ __forceinline__ uint32_t f2tf32(float x) {
    uint32_t r;
    asm("cvt.rna.tf32.f32 %0, %1;" : "=r"(r) : "f"(x));
    return r;
}

__device__ __forceinline__ uint32_t smem_to_u32(const void* smem_ptr) {
    uint32_t addr;
    asm("{ .reg .u64 tmp; cvta.to.shared.u64 tmp, %1; cvt.u32.u64 %0, tmp; }"
        : "=r"(addr) : "l"(smem_ptr));
    return addr;
}

__device__ __forceinline__ void cp_async16(uint32_t smem_addr, const void* gptr, uint32_t src_size) {
    asm volatile("cp.async.ca.shared.global [%0], [%1], 16, %2;"
                 :: "r"(smem_addr), "l"(gptr), "r"(src_size));
}
__device__ __forceinline__ void cp_async_commit() {
    asm volatile("cp.async.commit_group;" ::: "memory");
}
template <int N>
__device__ __forceinline__ void cp_async_wait() {
    asm volatile("cp.async.wait_group %0;" :: "n"(N) : "memory");
}

__device__ __forceinline__ void mma_tf32(float& c0, float& c1, float& c2, float& c3,
                                         uint32_t a0, uint32_t a1, uint32_t a2, uint32_t a3,
                                         uint32_t b0, uint32_t b1) {
    asm volatile(
        "mma.sync.aligned.m16n8k8.row.col.f32.tf32.tf32.f32 "
        "{%0,%1,%2,%3}, {%4,%5,%6,%7}, {%8,%9}, {%0,%1,%2,%3};"
        : "+f"(c0), "+f"(c1), "+f"(c2), "+f"(c3)
        : "r"(a0), "r"(a1), "r"(a2), "r"(a3), "r"(b0), "r"(b1));
}

// ---------------- sort-by-dst pipeline (per-relation scratch, rel = 0..2) ----------------
__global__ void zero_deg_kernel(int rel) {
    int i = blockIdx.x * blockDim.x + threadIdx.x;
    if (i < N_NODE) g_deg[rel * N_NODE + i] = 0;
}

__global__ void hist_kernel(int rel, const int* __restrict__ dst) {
    int i = blockIdx.x * blockDim.x + threadIdx.x;
    if (i < N_EDGE) atomicAdd(&g_deg[rel * N_NODE + __ldcs(dst + i)], 1);
}

__global__ void scan_block_kernel(int rel) {
    int t = threadIdx.x;
    int lane = t & 31, wid = t >> 5;
    int gidx = blockIdx.x * 1024 + t;
    int v = (gidx < N_NODE) ? g_deg[rel * N_NODE + gidx] : 0;
    int x = v;
    #pragma unroll
    for (int o = 1; o < 32; o <<= 1) {
        int y = __shfl_up_sync(0xFFFFFFFFu, x, o);
        if (lane >= o) x += y;
    }
    __shared__ int wsum[32];
    if (lane == 31) wsum[wid] = x;
    __syncthreads();
    if (wid == 0) {
        int w = wsum[lane];
        #pragma unroll
        for (int o = 1; o < 32; o <<= 1) {
            int y = __shfl_up_sync(0xFFFFFFFFu, w, o);
            if (lane >= o) w += y;
        }
        wsum[lane] = w;
    }
    __syncthreads();
    int incl = x + (wid ? wsum[wid - 1] : 0);
    if (gidx < N_NODE) g_offs[rel * (N_NODE + 1) + gidx] = incl - v;
    __syncthreads();
    if (t == 1023) g_bsum[rel * NBLK_SCAN + blockIdx.x] = wsum[31];
}

// fused: block-offset prefix computed in-block from g_bsum; writes final offs + cursor
__global__ void scan_add_kernel(int rel) {
    __shared__ int sh[NBLK_SCAN];
    int t = threadIdx.x;
    if (t < NBLK_SCAN) sh[t] = g_bsum[rel * NBLK_SCAN + t];
    __syncthreads();
    int boff = 0;
    for (int b = 0; b < blockIdx.x; ++b) boff += sh[b];   // uniform per block
    int gidx = blockIdx.x * 1024 + t;
    if (gidx < N_NODE) {
        int o = g_offs[rel * (N_NODE + 1) + gidx] + boff;
        g_offs[rel * (N_NODE + 1) + gidx] = o;
        g_cursor[rel * N_NODE + gidx] = o;
    }
    if (blockIdx.x == 0 && t == 0)
        g_offs[rel * (N_NODE + 1) + N_NODE] = N_EDGE;
}

__global__ void scatter_kernel(int rel, const int* __restrict__ src, const int* __restrict__ dst) {
    int i = blockIdx.x * blockDim.x + threadIdx.x;
    if (i < N_EDGE) {
        int pos = atomicAdd(&g_cursor[rel * N_NODE + __ldcs(dst + i)], 1);
        __stcs(&g_sorted_src[rel * N_EDGE + pos], __ldcs(src + i));
    }
}

// ---------------- aggregate: 64 threads, one 256-float slice of one node ----------------
// Output rows stored evict-first (.cs) so the dead output stream doesn't evict
// the hot 40MB gather slice from L2.
__global__ void aggregate_chunk_kernel(int rel, int dchunk,
                                       const float* __restrict__ xsrc,
                                       float* __restrict__ aggout) {
    int v = blockIdx.x;
    const int* offs = g_offs + rel * (N_NODE + 1);
    const int* srt  = g_sorted_src + rel * N_EDGE;
    int beg = offs[v];
    int end = offs[v + 1];
    int t = threadIdx.x;                       // 0..63
    const int qoff = dchunk * 64 + t;

    float4 acc = make_float4(0.f, 0.f, 0.f, 0.f);
    const float4* xs = reinterpret_cast<const float4*>(xsrc);
    int e = beg;
    for (; e + 7 < end; e += 8) {
        float4 r[8];
        #pragma unroll
        for (int j = 0; j < 8; j++)
            r[j] = xs[(size_t)__ldcs(srt + e + j) * (DIM / 4) + qoff];
        #pragma unroll
        for (int j = 0; j < 8; j++) {
            acc.x += r[j].x; acc.y += r[j].y; acc.z += r[j].z; acc.w += r[j].w;
        }
    }
    for (; e + 1 < end; e += 2) {
        float4 r0 = xs[(size_t)__ldcs(srt + e) * (DIM / 4) + qoff];
        float4 r1 = xs[(size_t)__ldcs(srt + e + 1) * (DIM / 4) + qoff];
        acc.x += r0.x + r1.x; acc.y += r0.y + r1.y;
        acc.z += r0.z + r1.z; acc.w += r0.w + r1.w;
    }
    if (e < end) {
        float4 r = xs[(size_t)__ldcs(srt + e) * (DIM / 4) + qoff];
        acc.x += r.x; acc.y += r.y; acc.z += r.z; acc.w += r.w;
    }
    int d = end - beg;
    float inv = 1.0f / (float)(d > 1 ? d : 1);
    float4 o;
    o.x = __uint_as_float(f2tf32(acc.x * inv));
    o.y = __uint_as_float(f2tf32(acc.y * inv));
    o.z = __uint_as_float(f2tf32(acc.z * inv));
    o.w = __uint_as_float(f2tf32(acc.w * inv));
    __stcs(reinterpret_cast<float4*>(aggout) + (size_t)v * (DIM / 4) + qoff, o);
}

// W[k][n] -> Wt[n][k], tf32(RNA)-rounded
__global__ void transpose_round_kernel(const float* __restrict__ W, float* __restrict__ Wt) {
    __shared__ float tile[32][33];
    int bx = blockIdx.x * 32, by = blockIdx.y * 32;
    int tx = threadIdx.x, ty = threadIdx.y;   // 32 x 8
    #pragma unroll
    for (int i = 0; i < 32; i += 8)
        tile[ty + i][tx] = W[(size_t)(by + ty + i) * DIM + bx + tx];
    __syncthreads();
    #pragma unroll
    for (int i = 0; i < 32; i += 8)
        Wt[(size_t)(bx + ty + i) * DIM + by + tx] = __uint_as_float(f2tf32(tile[tx][ty + i]));
}

// ---------------- cp.async-pipelined TF32 mma.sync GEMM body ----------------
#define LDR   20
#define ATILE (128 * LDR)
#define STAGE_FLOATS (2 * ATILE)
#define NSTAGE 3
#define GEMM_SMEM_DYN (NSTAGE * STAGE_FLOATS * 4)   // 61440 B

template <int CHUNKS>
__device__ __forceinline__ void gemm_body(
    int bm, int bn,
    const float* __restrict__ A0, const float* __restrict__ A1,
    const float* __restrict__ Wt0, const float* __restrict__ Wt1,
    const float* __restrict__ bias0, const float* __restrict__ bias1,
    float* __restrict__ C, int M, float* smem)
{
    const uint32_t smem_u32 = smem_to_u32(smem);

    const int t      = threadIdx.x;
    const int lane   = t & 31;
    const int warp   = t >> 5;
    const int warp_m = warp >> 2;
    const int warp_n = warp & 3;
    const int g      = lane >> 2;
    const int tid4   = lane & 3;

    const int KT = 64 * CHUNKS;

    const int s_row0 = t >> 2;
    const int s_row1 = (t + 256) >> 2;
    const int s_c    = t & 3;

    auto stage = [&](int kt, int buf) {
        const float* Asrc = (CHUNKS == 2 && kt >= 64) ? A1 : A0;
        const float* Wsrc = (CHUNKS == 2 && kt >= 64) ? Wt1 : Wt0;
        const int k0 = (kt & 63) * 16;
        const uint32_t abase = smem_u32 + (uint32_t)buf * (STAGE_FLOATS * 4);
        const uint32_t bbase = abase + ATILE * 4;
        #pragma unroll
        for (int i = 0; i < 2; i++) {
            int row = i ? s_row1 : s_row0;
            int gm = bm + row;
            int gmc = (gm < M) ? gm : 0;
            cp_async16(abase + (uint32_t)(row * LDR + s_c * 4) * 4,
                       Asrc + (size_t)gmc * DIM + k0 + s_c * 4,
                       (gm < M) ? 16u : 0u);
            int gn = bn + row;
            cp_async16(bbase + (uint32_t)(row * LDR + s_c * 4) * 4,
                       Wsrc + (size_t)gn * DIM + k0 + s_c * 4, 16u);
        }
    };

    float c[4][4][4];
    #pragma unroll
    for (int mt = 0; mt < 4; mt++)
        #pragma unroll
        for (int nt = 0; nt < 4; nt++)
            #pragma unroll
            for (int r = 0; r < 4; r++) c[mt][nt][r] = 0.f;

    auto compute = [&](int buf) {
        const uint32_t* As = reinterpret_cast<const uint32_t*>(smem) + buf * STAGE_FLOATS;
        const uint32_t* Bs = As + ATILE;
        #pragma unroll
        for (int ks = 0; ks < 2; ks++) {
            const int kb = ks * 8;
            uint32_t a[4][4], b[4][2];
            #pragma unroll
            for (int mt = 0; mt < 4; mt++) {
                const uint32_t* ar0 = As + (warp_m * 64 + mt * 16 + g) * LDR + kb + tid4;
                const uint32_t* ar1 = ar0 + 8 * LDR;
                a[mt][0] = ar0[0]; a[mt][1] = ar1[0];
                a[mt][2] = ar0[4]; a[mt][3] = ar1[4];
            }
            #pragma unroll
            for (int nt = 0; nt < 4; nt++) {
                const uint32_t* br = Bs + (warp_n * 32 + nt * 8 + g) * LDR + kb + tid4;
                b[nt][0] = br[0]; b[nt][1] = br[4];
            }
            #pragma unroll
            for (int mt = 0; mt < 4; mt++)
                #pragma unroll
                for (int nt = 0; nt < 4; nt++)
                    mma_tf32(c[mt][nt][0], c[mt][nt][1], c[mt][nt][2], c[mt][nt][3],
                             a[mt][0], a[mt][1], a[mt][2], a[mt][3],
                             b[nt][0], b[nt][1]);
        }
    };

    stage(0, 0); cp_async_commit();
    stage(1, 1); cp_async_commit();

    int buf = 0;
    for (int kt = 0; kt < KT; ++kt) {
        cp_async_wait<1>();
        __syncthreads();
        compute(buf);
        if (kt + 2 < KT) stage(kt + 2, (buf + 2) % NSTAGE);
        cp_async_commit();
        buf = (buf + 1) % NSTAGE;
    }

    // C stores evict-first: dead stream, keep A/W tiles resident in L2
    #pragma unroll
    for (int mt = 0; mt < 4; mt++) {
        int r0 = bm + warp_m * 64 + mt * 16 + g;
        int r1 = r0 + 8;
        #pragma unroll
        for (int nt = 0; nt < 4; nt++) {
            int col = bn + warp_n * 32 + nt * 8 + tid4 * 2;
            float bv0 = bias0[col], bv1 = bias0[col + 1];
            if (CHUNKS == 2) { bv0 += bias1[col]; bv1 += bias1[col + 1]; }
            if (r0 < M) {
                float* p = &C[(size_t)r0 * DIM + col];
                __stcs(reinterpret_cast<float2*>(p),
                       make_float2(c[mt][nt][0] + bv0, c[mt][nt][1] + bv1));
            }
            if (r1 < M) {
                float* p = &C[(size_t)r1 * DIM + col];
                __stcs(reinterpret_cast<float2*>(p),
                       make_float2(c[mt][nt][2] + bv0, c[mt][nt][3] + bv1));
            }
        }
    }
}

// combined GEMM launch: blocks [0, GEMM_BLOCKS) = prot (K=2048, dpi+ppi);
// blocks [GEMM_BLOCKS, 2*GEMM_BLOCKS) = ddi (K=1024).
__global__ __launch_bounds__(256, 2) void gemm_combined_kernel(
    const float* __restrict__ A0, const float* __restrict__ A1,
    const float* __restrict__ Wt0, const float* __restrict__ Wt1,
    const float* __restrict__ bias0, const float* __restrict__ bias1,
    float* __restrict__ Cprot,
    const float* __restrict__ A2, const float* __restrict__ Wt2,
    const float* __restrict__ bias2, float* __restrict__ Cdrug, int M)
{
    extern __shared__ float smem[];
    if (blockIdx.x < GEMM_BLOCKS) {
        int bm = (blockIdx.x / GEMM_NBLKS) * 128;
        int bn = (blockIdx.x % GEMM_NBLKS) * 128;
        gemm_body<2>(bm, bn, A0, A1, Wt0, Wt1, bias0, bias1, Cprot, M, smem);
    } else {
        int b = blockIdx.x - GEMM_BLOCKS;
        int bm = (b / GEMM_NBLKS) * 128;
        int bn = (b % GEMM_NBLKS) * 128;
        gemm_body<1>(bm, bn, A2, nullptr, Wt2, nullptr, bias2, nullptr, Cdrug, M, smem);
    }
}

// ---------------- launch (single capture stream) ----------------
static void run_sort(int rel, const int* src, const int* dst)
{
    zero_deg_kernel<<<(N_NODE + 255) / 256, 256>>>(rel);
    hist_kernel<<<(N_EDGE + 255) / 256, 256>>>(rel, dst);
    scan_block_kernel<<<NBLK_SCAN, 1024>>>(rel);
    scan_add_kernel<<<NBLK_SCAN, 1024>>>(rel);
    scatter_kernel<<<(N_EDGE + 255) / 256, 256>>>(rel, src, dst);
}

extern "C" void kernel_launch(void* const* d_in, const int* in_sizes, int n_in,
                              void* d_out, int out_size)
{
    const float* x_drug = (const float*)d_in[0];
    const float* x_prot = (const float*)d_in[1];
    const float* W_ddi  = (const float*)d_in[2];
    const float* b_ddi  = (const float*)d_in[3];
    const float* W_dpi  = (const float*)d_in[4];
    const float* b_dpi  = (const float*)d_in[5];
    const float* W_ppi  = (const float*)d_in[6];
    const float* b_ppi  = (const float*)d_in[7];
    const int* src_ddi  = (const int*)d_in[8];
    const int* dst_ddi  = (const int*)d_in[9];
    const int* src_dpi  = (const int*)d_in[10];
    const int* dst_dpi  = (const int*)d_in[11];
    const int* src_ppi  = (const int*)d_in[12];
    const int* dst_ppi  = (const int*)d_in[13];

    float* out_drug = (float*)d_out;
    float* out_prot = out_drug + (size_t)N_NODE * DIM;

    float* agg0; cudaGetSymbolAddress((void**)&agg0, g_agg0);   // dpi
    float* agg1; cudaGetSymbolAddress((void**)&agg1, g_agg1);   // ppi
    float* agg2; cudaGetSymbolAddress((void**)&agg2, g_agg2);   // ddi
    float* wt0;  cudaGetSymbolAddress((void**)&wt0,  g_wt0);
    float* wt1;  cudaGetSymbolAddress((void**)&wt1,  g_wt1);
    float* wt2;  cudaGetSymbolAddress((void**)&wt2,  g_wt2);

    cudaFuncSetAttribute(gemm_combined_kernel,
                         cudaFuncAttributeMaxDynamicSharedMemorySize, GEMM_SMEM_DYN);

    dim3 tgrid(32, 32), tblk(32, 8);

    // ---- all sorts up front ----
    run_sort(0, src_dpi, dst_dpi);
    run_sort(1, src_ppi, dst_ppi);
    run_sort(2, src_ddi, dst_ddi);

    // ---- weight transposes ----
    transpose_round_kernel<<<tgrid, tblk>>>(W_dpi, wt0);
    transpose_round_kernel<<<tgrid, tblk>>>(W_ppi, wt1);
    transpose_round_kernel<<<tgrid, tblk>>>(W_ddi, wt2);

    // ---- aggregates: interleave dpi+ddi (both gather x_drug -> shared L2 slice),
    //      then ppi (x_prot) alone ----
    for (int c = 0; c < DCHUNKS; ++c) {
        aggregate_chunk_kernel<<<N_NODE, 64>>>(0, c, x_drug, agg0);
        aggregate_chunk_kernel<<<N_NODE, 64>>>(2, c, x_drug, agg2);
    }
    for (int c = 0; c < DCHUNKS; ++c)
        aggregate_chunk_kernel<<<N_NODE, 64>>>(1, c, x_prot, agg1);

    // ---- single combined GEMM launch: prot (K=2048) + ddi (K=1024) ----
    gemm_combined_kernel<<<2 * GEMM_BLOCKS, 256, GEMM_SMEM_DYN>>>(
        agg0, agg1, wt0, wt1, b_dpi, b_ppi, out_prot,
        agg2, wt2, b_ddi, out_drug, N_NODE);
}

// round 13
// speedup vs baseline: 1.3100x; 1.1855x over previous
#include <cuda_runtime.h>
#include <cuda_bf16.h>
#include <cstdint>

// Problem constants
#define N_NODE 40000
#define N_EDGE 320000
#define DIM    1024
#define NBLK_SCAN 40            // ceil(40000/1024)
#define DCHUNKS 2               // 2 x 512-float slices

#define GEMM_MBLKS ((N_NODE + 127) / 128)     // 313
#define GEMM_NBLKS (DIM / 128)                // 8
#define GEMM_BLOCKS (GEMM_MBLKS * GEMM_NBLKS) // 2504

// ---------------- device scratch (no cudaMalloc allowed) ----------------
__device__ int   g_deg[3 * N_NODE];
__device__ int   g_offs[3 * (N_NODE + 1)];
__device__ int   g_cursor[3 * N_NODE];
__device__ int   g_sorted_src[3 * N_EDGE];
__device__ int   g_bsum[3 * NBLK_SCAN];
__device__ float g_agg0[(size_t)N_NODE * DIM];   // dpi
__device__ float g_agg1[(size_t)N_NODE * DIM];   // ppi
__device__ float g_agg2[(size_t)N_NODE * DIM];   // ddi
__device__ float g_wt0[(size_t)DIM * DIM];
__device__ float g_wt1[(size_t)DIM * DIM];
__device__ float g_wt2[(size_t)DIM * DIM];

// ---------------- helpers ----------------
__device__ __forceinline__ uint32_t f2tf32(float x) {
    uint32_t r;
    asm("cvt.rna.tf32.f32 %0, %1;" : "=r"(r) : "f"(x));
    return r;
}

__device__ __forceinline__ uint32_t smem_to_u32(const void* smem_ptr) {
    uint32_t addr;
    asm("{ .reg .u64 tmp; cvta.to.shared.u64 tmp, %1; cvt.u32.u64 %0, tmp; }"
        : "=r"(addr) : "l"(smem_ptr));
    return addr;
}

__device__ __forceinline__ void cp_async16(uint32_t smem_addr, const void* gptr, uint32_t src_size) {
    asm volatile("cp.async.ca.shared.global [%0], [%1], 16, %2;"
                 :: "r"(smem_addr), "l"(gptr), "r"(src_size));
}
__device__ __forceinline__ void cp_async_commit() {
    asm volatile("cp.async.commit_group;" ::: "memory");
}
template <int N>
__device__ __forceinline__ void cp_async_wait() {
    asm volatile("cp.async.wait_group %0;" :: "n"(N) : "memory");
}

__device__ __forceinline__ void ldsm_x4(uint32_t* r, uint32_t addr) {
    asm volatile("ldmatrix.sync.aligned.m8n8.x4.shared.b16 {%0,%1,%2,%3}, [%4];"
                 : "=r"(r[0]), "=r"(r[1]), "=r"(r[2]), "=r"(r[3]) : "r"(addr));
}
__device__ __forceinline__ void ldsm_x2(uint32_t* r, uint32_t addr) {
    asm volatile("ldmatrix.sync.aligned.m8n8.x2.shared.b16 {%0,%1}, [%2];"
                 : "=r"(r[0]), "=r"(r[1]) : "r"(addr));
}

__device__ __forceinline__ void mma_tf32(float& c0, float& c1, float& c2, float& c3,
                                         uint32_t a0, uint32_t a1, uint32_t a2, uint32_t a3,
                                         uint32_t b0, uint32_t b1) {
    asm volatile(
        "mma.sync.aligned.m16n8k8.row.col.f32.tf32.tf32.f32 "
        "{%0,%1,%2,%3}, {%4,%5,%6,%7}, {%8,%9}, {%0,%1,%2,%3};"
        : "+f"(c0), "+f"(c1), "+f"(c2), "+f"(c3)
        : "r"(a0), "r"(a1), "r"(a2), "r"(a3), "r"(b0), "r"(b1));
}

// ---------------- sort-by-dst pipeline (per-relation scratch, rel = 0..2) ----------------
__global__ void zero_deg_kernel(int rel) {
    int i = blockIdx.x * blockDim.x + threadIdx.x;
    if (i < N_NODE) g_deg[rel * N_NODE + i] = 0;
}

__global__ void hist_kernel(int rel, const int* __restrict__ dst) {
    int i = blockIdx.x * blockDim.x + threadIdx.x;
    if (i < N_EDGE) atomicAdd(&g_deg[rel * N_NODE + __ldcs(dst + i)], 1);
}

__global__ void scan_block_kernel(int rel) {
    int t = threadIdx.x;
    int lane = t & 31, wid = t >> 5;
    int gidx = blockIdx.x * 1024 + t;
    int v = (gidx < N_NODE) ? g_deg[rel * N_NODE + gidx] : 0;
    int x = v;
    #pragma unroll
    for (int o = 1; o < 32; o <<= 1) {
        int y = __shfl_up_sync(0xFFFFFFFFu, x, o);
        if (lane >= o) x += y;
    }
    __shared__ int wsum[32];
    if (lane == 31) wsum[wid] = x;
    __syncthreads();
    if (wid == 0) {
        int w = wsum[lane];
        #pragma unroll
        for (int o = 1; o < 32; o <<= 1) {
            int y = __shfl_up_sync(0xFFFFFFFFu, w, o);
            if (lane >= o) w += y;
        }
        wsum[lane] = w;
    }
    __syncthreads();
    int incl = x + (wid ? wsum[wid - 1] : 0);
    if (gidx < N_NODE) g_offs[rel * (N_NODE + 1) + gidx] = incl - v;
    __syncthreads();
    if (t == 1023) g_bsum[rel * NBLK_SCAN + blockIdx.x] = wsum[31];
}

__global__ void scan_add_kernel(int rel) {
    __shared__ int sh[NBLK_SCAN];
    int t = threadIdx.x;
    if (t < NBLK_SCAN) sh[t] = g_bsum[rel * NBLK_SCAN + t];
    __syncthreads();
    int boff = 0;
    for (int b = 0; b < blockIdx.x; ++b) boff += sh[b];
    int gidx = blockIdx.x * 1024 + t;
    if (gidx < N_NODE) {
        int o = g_offs[rel * (N_NODE + 1) + gidx] + boff;
        g_offs[rel * (N_NODE + 1) + gidx] = o;
        g_cursor[rel * N_NODE + gidx] = o;
    }
    if (blockIdx.x == 0 && t == 0)
        g_offs[rel * (N_NODE + 1) + N_NODE] = N_EDGE;
}

__global__ void scatter_kernel(int rel, const int* __restrict__ src, const int* __restrict__ dst) {
    int i = blockIdx.x * blockDim.x + threadIdx.x;
    if (i < N_EDGE) {
        int pos = atomicAdd(&g_cursor[rel * N_NODE + __ldcs(dst + i)], 1);
        __stcs(&g_sorted_src[rel * N_EDGE + pos], __ldcs(src + i));
    }
}

// ---------------- aggregate: 128 threads, one 512-float slice of one node ----------------
__global__ void aggregate_chunk_kernel(int rel, int dchunk,
                                       const float* __restrict__ xsrc,
                                       float* __restrict__ aggout) {
    int v = blockIdx.x;
    const int* offs = g_offs + rel * (N_NODE + 1);
    const int* srt  = g_sorted_src + rel * N_EDGE;
    int beg = offs[v];
    int end = offs[v + 1];
    int t = threadIdx.x;                       // 0..127
    const int qoff = dchunk * 128 + t;

    float4 acc = make_float4(0.f, 0.f, 0.f, 0.f);
    const float4* xs = reinterpret_cast<const float4*>(xsrc);
    int e = beg;
    for (; e + 7 < end; e += 8) {
        float4 r[8];
        #pragma unroll
        for (int j = 0; j < 8; j++)
            r[j] = xs[(size_t)__ldcs(srt + e + j) * (DIM / 4) + qoff];
        #pragma unroll
        for (int j = 0; j < 8; j++) {
            acc.x += r[j].x; acc.y += r[j].y; acc.z += r[j].z; acc.w += r[j].w;
        }
    }
    for (; e + 1 < end; e += 2) {
        float4 r0 = xs[(size_t)__ldcs(srt + e) * (DIM / 4) + qoff];
        float4 r1 = xs[(size_t)__ldcs(srt + e + 1) * (DIM / 4) + qoff];
        acc.x += r0.x + r1.x; acc.y += r0.y + r1.y;
        acc.z += r0.z + r1.z; acc.w += r0.w + r1.w;
    }
    if (e < end) {
        float4 r = xs[(size_t)__ldcs(srt + e) * (DIM / 4) + qoff];
        acc.x += r.x; acc.y += r.y; acc.z += r.z; acc.w += r.w;
    }
    int d = end - beg;
    float inv = 1.0f / (float)(d > 1 ? d : 1);
    float4 o;
    o.x = __uint_as_float(f2tf32(acc.x * inv));
    o.y = __uint_as_float(f2tf32(acc.y * inv));
    o.z = __uint_as_float(f2tf32(acc.z * inv));
    o.w = __uint_as_float(f2tf32(acc.w * inv));
    __stcs(reinterpret_cast<float4*>(aggout) + (size_t)v * (DIM / 4) + qoff, o);
}

// W[k][n] -> Wt[n][k], tf32(RNA)-rounded
__global__ void transpose_round_kernel(const float* __restrict__ W, float* __restrict__ Wt) {
    __shared__ float tile[32][33];
    int bx = blockIdx.x * 32, by = blockIdx.y * 32;
    int tx = threadIdx.x, ty = threadIdx.y;   // 32 x 8
    #pragma unroll
    for (int i = 0; i < 32; i += 8)
        tile[ty + i][tx] = W[(size_t)(by + ty + i) * DIM + bx + tx];
    __syncthreads();
    #pragma unroll
    for (int i = 0; i < 32; i += 8)
        Wt[(size_t)(bx + ty + i) * DIM + by + tx] = __uint_as_float(f2tf32(tile[tx][ty + i]));
}

// ---------------- cp.async + ldmatrix TF32 mma.sync GEMM ----------------
// BK = 32 floats = 128B row = one SW128 atom. Chunk swizzle: c' = c ^ (row & 7).
// A/B tiles 128x32 floats = 16KB each; 3-stage ring = 96KB dynamic smem.
#define TILE_BYTES   16384
#define STAGE_BYTES  (2 * TILE_BYTES)
#define NSTAGE 3
#define GEMM_SMEM_DYN (NSTAGE * STAGE_BYTES)   // 98304 B

template <int CHUNKS>
__device__ __forceinline__ void gemm_body(
    int bm, int bn,
    const float* __restrict__ A0, const float* __restrict__ A1,
    const float* __restrict__ Wt0, const float* __restrict__ Wt1,
    const float* __restrict__ bias0, const float* __restrict__ bias1,
    float* __restrict__ C, int M, float* smem)
{
    const uint32_t smem_u32 = smem_to_u32(smem);

    const int t      = threadIdx.x;
    const int lane   = t & 31;
    const int warp   = t >> 5;
    const int warp_m = warp >> 2;
    const int warp_n = warp & 3;
    const int g      = lane >> 2;
    const int tid4   = lane & 3;
    const int lane7  = lane & 7;

    const int KT = 32 * CHUNKS;   // BK=32 tiles

    // staging indices: idx = t + it*256 in [0,1024): row = idx>>3, c = idx&7
    const int s_row = t >> 3;     // + it*32
    const int s_c   = t & 7;

    auto stage = [&](int kt, int buf) {
        const float* Asrc = (CHUNKS == 2 && kt >= 32) ? A1 : A0;
        const float* Wsrc = (CHUNKS == 2 && kt >= 32) ? Wt1 : Wt0;
        const int k0 = (kt & 31) * 32;                 // float offset
        const uint32_t abase = smem_u32 + (uint32_t)buf * STAGE_BYTES;
        const uint32_t bbase = abase + TILE_BYTES;
        #pragma unroll
        for (int it = 0; it < 4; ++it) {
            int row = s_row + it * 32;                 // 0..127
            uint32_t dst = (uint32_t)(row * 128 + ((s_c ^ (row & 7)) * 16));
            int gm = bm + row;
            int gmc = (gm < M) ? gm : 0;
            cp_async16(abase + dst, Asrc + (size_t)gmc * DIM + k0 + s_c * 4,
                       (gm < M) ? 16u : 0u);
            int gn = bn + row;
            cp_async16(bbase + dst, Wsrc + (size_t)gn * DIM + k0 + s_c * 4, 16u);
        }
    };

    // ldmatrix address components (loop-invariant)
    uint32_t rowoff_a[4], rowoff_b[4], cka[4], ckb[4];
    {
        int khia = lane >> 4;          // 0/1: k-lo / k-hi half for A (x4)
        int khib = (lane >> 3) & 1;    // 0/1 for B (x2)
        #pragma unroll
        for (int mt = 0; mt < 4; mt++)
            rowoff_a[mt] = (uint32_t)((warp_m * 64 + mt * 16 + (lane & 15)) * 128);
        #pragma unroll
        for (int nt = 0; nt < 4; nt++)
            rowoff_b[nt] = (uint32_t)((warp_n * 32 + nt * 8 + lane7) * 128);
        #pragma unroll
        for (int k = 0; k < 4; k++) {
            cka[k] = (uint32_t)((((2 * k + khia) ^ lane7)) * 16);
            ckb[k] = (uint32_t)((((2 * k + khib) ^ lane7)) * 16);
        }
    }

    float c[4][4][4];
    #pragma unroll
    for (int mt = 0; mt < 4; mt++)
        #pragma unroll
        for (int nt = 0; nt < 4; nt++)
            #pragma unroll
            for (int r = 0; r < 4; r++) c[mt][nt][r] = 0.f;

    auto compute = [&](int buf) {
        const uint32_t abase = smem_u32 + (uint32_t)buf * STAGE_BYTES;
        const uint32_t bbase = abase + TILE_BYTES;
        #pragma unroll
        for (int kstep = 0; kstep < 4; ++kstep) {
            uint32_t a[4][4], b[4][2];
            #pragma unroll
            for (int mt = 0; mt < 4; mt++)
                ldsm_x4(a[mt], abase + rowoff_a[mt] + cka[kstep]);
            #pragma unroll
            for (int nt = 0; nt < 4; nt++)
                ldsm_x2(b[nt], bbase + rowoff_b[nt] + ckb[kstep]);
            #pragma unroll
            for (int mt = 0; mt < 4; mt++)
                #pragma unroll
                for (int nt = 0; nt < 4; nt++)
                    mma_tf32(c[mt][nt][0], c[mt][nt][1], c[mt][nt][2], c[mt][nt][3],
                             a[mt][0], a[mt][1], a[mt][2], a[mt][3],
                             b[nt][0], b[nt][1]);
        }
    };

    stage(0, 0); cp_async_commit();
    stage(1, 1); cp_async_commit();

    int buf = 0;
    for (int kt = 0; kt < KT; ++kt) {
        cp_async_wait<1>();
        __syncthreads();
        compute(buf);
        if (kt + 2 < KT) stage(kt + 2, (buf + 2) % NSTAGE);
        cp_async_commit();
        buf = (buf + 1) % NSTAGE;
    }

    // C stores evict-first: dead stream
    #pragma unroll
    for (int mt = 0; mt < 4; mt++) {
        int r0 = bm + warp_m * 64 + mt * 16 + g;
        int r1 = r0 + 8;
        #pragma unroll
        for (int nt = 0; nt < 4; nt++) {
            int col = bn + warp_n * 32 + nt * 8 + tid4 * 2;
            float bv0 = bias0[col], bv1 = bias0[col + 1];
            if (CHUNKS == 2) { bv0 += bias1[col]; bv1 += bias1[col + 1]; }
            if (r0 < M) {
                float* p = &C[(size_t)r0 * DIM + col];
                __stcs(reinterpret_cast<float2*>(p),
                       make_float2(c[mt][nt][0] + bv0, c[mt][nt][1] + bv1));
            }
            if (r1 < M) {
                float* p = &C[(size_t)r1 * DIM + col];
                __stcs(reinterpret_cast<float2*>(p),
                       make_float2(c[mt][nt][2] + bv0, c[mt][nt][3] + bv1));
            }
        }
    }
}

// combined GEMM launch: blocks [0, GEMM_BLOCKS) = prot (K=2048, dpi+ppi);
// blocks [GEMM_BLOCKS, 2*GEMM_BLOCKS) = ddi (K=1024).
__global__ __launch_bounds__(256, 2) void gemm_combined_kernel(
    const float* __restrict__ A0, const float* __restrict__ A1,
    const float* __restrict__ Wt0, const float* __restrict__ Wt1,
    const float* __restrict__ bias0, const float* __restrict__ bias1,
    float* __restrict__ Cprot,
    const float* __restrict__ A2, const float* __restrict__ Wt2,
    const float* __restrict__ bias2, float* __restrict__ Cdrug, int M)
{
    extern __shared__ float smem[];
    if (blockIdx.x < GEMM_BLOCKS) {
        int bm = (blockIdx.x / GEMM_NBLKS) * 128;
        int bn = (blockIdx.x % GEMM_NBLKS) * 128;
        gemm_body<2>(bm, bn, A0, A1, Wt0, Wt1, bias0, bias1, Cprot, M, smem);
    } else {
        int b = blockIdx.x - GEMM_BLOCKS;
        int bm = (b / GEMM_NBLKS) * 128;
        int bn = (b % GEMM_NBLKS) * 128;
        gemm_body<1>(bm, bn, A2, nullptr, Wt2, nullptr, bias2, nullptr, Cdrug, M, smem);
    }
}

// ---------------- launch (single capture stream) ----------------
static void run_sort(int rel, const int* src, const int* dst)
{
    zero_deg_kernel<<<(N_NODE + 255) / 256, 256>>>(rel);
    hist_kernel<<<(N_EDGE + 255) / 256, 256>>>(rel, dst);
    scan_block_kernel<<<NBLK_SCAN, 1024>>>(rel);
    scan_add_kernel<<<NBLK_SCAN, 1024>>>(rel);
    scatter_kernel<<<(N_EDGE + 255) / 256, 256>>>(rel, src, dst);
}

extern "C" void kernel_launch(void* const* d_in, const int* in_sizes, int n_in,
                              void* d_out, int out_size)
{
    const float* x_drug = (const float*)d_in[0];
    const float* x_prot = (const float*)d_in[1];
    const float* W_ddi  = (const float*)d_in[2];
    const float* b_ddi  = (const float*)d_in[3];
    const float* W_dpi  = (const float*)d_in[4];
    const float* b_dpi  = (const float*)d_in[5];
    const float* W_ppi  = (const float*)d_in[6];
    const float* b_ppi  = (const float*)d_in[7];
    const int* src_ddi  = (const int*)d_in[8];
    const int* dst_ddi  = (const int*)d_in[9];
    const int* src_dpi  = (const int*)d_in[10];
    const int* dst_dpi  = (const int*)d_in[11];
    const int* src_ppi  = (const int*)d_in[12];
    const int* dst_ppi  = (const int*)d_in[13];

    float* out_drug = (float*)d_out;
    float* out_prot = out_drug + (size_t)N_NODE * DIM;

    float* agg0; cudaGetSymbolAddress((void**)&agg0, g_agg0);   // dpi
    float* agg1; cudaGetSymbolAddress((void**)&agg1, g_agg1);   // ppi
    float* agg2; cudaGetSymbolAddress((void**)&agg2, g_agg2);   // ddi
    float* wt0;  cudaGetSymbolAddress((void**)&wt0,  g_wt0);
    float* wt1;  cudaGetSymbolAddress((void**)&wt1,  g_wt1);
    float* wt2;  cudaGetSymbolAddress((void**)&wt2,  g_wt2);

    cudaFuncSetAttribute(gemm_combined_kernel,
                         cudaFuncAttributeMaxDynamicSharedMemorySize, GEMM_SMEM_DYN);

    dim3 tgrid(32, 32), tblk(32, 8);

    // ---- all sorts up front ----
    run_sort(0, src_dpi, dst_dpi);
    run_sort(1, src_ppi, dst_ppi);
    run_sort(2, src_ddi, dst_ddi);

    // ---- weight transposes ----
    transpose_round_kernel<<<tgrid, tblk>>>(W_dpi, wt0);
    transpose_round_kernel<<<tgrid, tblk>>>(W_ppi, wt1);
    transpose_round_kernel<<<tgrid, tblk>>>(W_ddi, wt2);

    // ---- aggregates: interleave dpi+ddi (both gather x_drug), then ppi ----
    for (int c = 0; c < DCHUNKS; ++c) {
        aggregate_chunk_kernel<<<N_NODE, 128>>>(0, c, x_drug, agg0);
        aggregate_chunk_kernel<<<N_NODE, 128>>>(2, c, x_drug, agg2);
    }
    for (int c = 0; c < DCHUNKS; ++c)
        aggregate_chunk_kernel<<<N_NODE, 128>>>(1, c, x_prot, agg1);

    // ---- single combined GEMM launch: prot (K=2048) + ddi (K=1024) ----
    gemm_combined_kernel<<<2 * GEMM_BLOCKS, 256, GEMM_SMEM_DYN>>>(
        agg0, agg1, wt0, wt1, b_dpi, b_ppi, out_prot,
        agg2, wt2, b_ddi, out_drug, N_NODE);
}

// round 15
// speedup vs baseline: 1.3748x; 1.0495x over previous
#include <cuda_runtime.h>
#include <cuda_bf16.h>
#include <cstdint>

// Problem constants
#define N_NODE 40000
#define N_EDGE 320000
#define DIM    1024
#define NBLK_SCAN 40            // ceil(40000/1024)
#define DCHUNKS 2               // 2 x 512-float slices

#define GEMM_MBLKS ((N_NODE + 255) / 256)     // 157 (BM=256)
#define GEMM_NBLKS (DIM / 128)                // 8
#define GEMM_BLOCKS (GEMM_MBLKS * GEMM_NBLKS) // 1256

// ---------------- device scratch (no cudaMalloc allowed) ----------------
__device__ int   g_deg[3 * N_NODE];
__device__ int   g_offs[3 * (N_NODE + 1)];
__device__ int   g_cursor[3 * N_NODE];
__device__ int   g_sorted_src[3 * N_EDGE];
__device__ int   g_bsum[3 * NBLK_SCAN];
__device__ float g_agg0[(size_t)N_NODE * DIM];   // dpi
__device__ float g_agg1[(size_t)N_NODE * DIM];   // ppi
__device__ float g_agg2[(size_t)N_NODE * DIM];   // ddi
__device__ float g_wt0[(size_t)DIM * DIM];
__device__ float g_wt1[(size_t)DIM * DIM];
__device__ float g_wt2[(size_t)DIM * DIM];

// ---------------- helpers ----------------
__device__ __forceinline__ uint32_t f2tf32(float x) {
    uint32_t r;
    asm("cvt.rna.tf32.f32 %0, %1;" : "=r"(r) : "f"(x));
    return r;
}

__device__ __forceinline__ uint32_t smem_to_u32(const void* smem_ptr) {
    uint32_t addr;
    asm("{ .reg .u64 tmp; cvta.to.shared.u64 tmp, %1; cvt.u32.u64 %0, tmp; }"
        : "=r"(addr) : "l"(smem_ptr));
    return addr;
}

__device__ __forceinline__ void cp_async16(uint32_t smem_addr, const void* gptr, uint32_t src_size) {
    asm volatile("cp.async.ca.shared.global [%0], [%1], 16, %2;"
                 :: "r"(smem_addr), "l"(gptr), "r"(src_size));
}
__device__ __forceinline__ void cp_async_commit() {
    asm volatile("cp.async.commit_group;" ::: "memory");
}
template <int N>
__device__ __forceinline__ void cp_async_wait() {
    asm volatile("cp.async.wait_group %0;" :: "n"(N) : "memory");
}

__device__ __forceinline__ void ldsm_x4(uint32_t* r, uint32_t addr) {
    asm volatile("ldmatrix.sync.aligned.m8n8.x4.shared.b16 {%0,%1,%2,%3}, [%4];"
                 : "=r"(r[0]), "=r"(r[1]), "=r"(r[2]), "=r"(r[3]) : "r"(addr));
}

__device__ __forceinline__ void mma_tf32(float& c0, float& c1, float& c2, float& c3,
                                         uint32_t a0, uint32_t a1, uint32_t a2, uint32_t a3,
                                         uint32_t b0, uint32_t b1) {
    asm volatile(
        "mma.sync.aligned.m16n8k8.row.col.f32.tf32.tf32.f32 "
        "{%0,%1,%2,%3}, {%4,%5,%6,%7}, {%8,%9}, {%0,%1,%2,%3};"
        : "+f"(c0), "+f"(c1), "+f"(c2), "+f"(c3)
        : "r"(a0), "r"(a1), "r"(a2), "r"(a3), "r"(b0), "r"(b1));
}

// ---------------- sort-by-dst pipeline (per-relation scratch, rel = 0..2) ----------------
__global__ void zero_deg_kernel(int rel) {
    int i = blockIdx.x * blockDim.x + threadIdx.x;
    if (i < N_NODE) g_deg[rel * N_NODE + i] = 0;
}

__global__ void hist_kernel(int rel, const int* __restrict__ dst) {
    int i = blockIdx.x * blockDim.x + threadIdx.x;
    if (i < N_EDGE) atomicAdd(&g_deg[rel * N_NODE + __ldcs(dst + i)], 1);
}

__global__ void scan_block_kernel(int rel) {
    int t = threadIdx.x;
    int lane = t & 31, wid = t >> 5;
    int gidx = blockIdx.x * 1024 + t;
    int v = (gidx < N_NODE) ? g_deg[rel * N_NODE + gidx] : 0;
    int x = v;
    #pragma unroll
    for (int o = 1; o < 32; o <<= 1) {
        int y = __shfl_up_sync(0xFFFFFFFFu, x, o);
        if (lane >= o) x += y;
    }
    __shared__ int wsum[32];
    if (lane == 31) wsum[wid] = x;
    __syncthreads();
    if (wid == 0) {
        int w = wsum[lane];
        #pragma unroll
        for (int o = 1; o < 32; o <<= 1) {
            int y = __shfl_up_sync(0xFFFFFFFFu, w, o);
            if (lane >= o) w += y;
        }
        wsum[lane] = w;
    }
    __syncthreads();
    int incl = x + (wid ? wsum[wid - 1] : 0);
    if (gidx < N_NODE) g_offs[rel * (N_NODE + 1) + gidx] = incl - v;
    __syncthreads();
    if (t == 1023) g_bsum[rel * NBLK_SCAN + blockIdx.x] = wsum[31];
}

__global__ void scan_add_kernel(int rel) {
    __shared__ int sh[NBLK_SCAN];
    int t = threadIdx.x;
    if (t < NBLK_SCAN) sh[t] = g_bsum[rel * NBLK_SCAN + t];
    __syncthreads();
    int boff = 0;
    for (int b = 0; b < blockIdx.x; ++b) boff += sh[b];
    int gidx = blockIdx.x * 1024 + t;
    if (gidx < N_NODE) {
        int o = g_offs[rel * (N_NODE + 1) + gidx] + boff;
        g_offs[rel * (N_NODE + 1) + gidx] = o;
        g_cursor[rel * N_NODE + gidx] = o;
    }
    if (blockIdx.x == 0 && t == 0)
        g_offs[rel * (N_NODE + 1) + N_NODE] = N_EDGE;
}

__global__ void scatter_kernel(int rel, const int* __restrict__ src, const int* __restrict__ dst) {
    int i = blockIdx.x * blockDim.x + threadIdx.x;
    if (i < N_EDGE) {
        int pos = atomicAdd(&g_cursor[rel * N_NODE + __ldcs(dst + i)], 1);
        __stcs(&g_sorted_src[rel * N_EDGE + pos], __ldcs(src + i));
    }
}

// ---------------- aggregate: 128 threads, one 512-float slice of one node ----------------
__global__ void aggregate_chunk_kernel(int rel, int dchunk,
                                       const float* __restrict__ xsrc,
                                       float* __restrict__ aggout) {
    int v = blockIdx.x;
    const int* offs = g_offs + rel * (N_NODE + 1);
    const int* srt  = g_sorted_src + rel * N_EDGE;
    int beg = offs[v];
    int end = offs[v + 1];
    int t = threadIdx.x;                       // 0..127
    const int qoff = dchunk * 128 + t;

    float4 acc = make_float4(0.f, 0.f, 0.f, 0.f);
    const float4* xs = reinterpret_cast<const float4*>(xsrc);
    int e = beg;
    for (; e + 7 < end; e += 8) {
        float4 r[8];
        #pragma unroll
        for (int j = 0; j < 8; j++)
            r[j] = xs[(size_t)__ldcs(srt + e + j) * (DIM / 4) + qoff];
        #pragma unroll
        for (int j = 0; j < 8; j++) {
            acc.x += r[j].x; acc.y += r[j].y; acc.z += r[j].z; acc.w += r[j].w;
        }
    }
    for (; e + 1 < end; e += 2) {
        float4 r0 = xs[(size_t)__ldcs(srt + e) * (DIM / 4) + qoff];
        float4 r1 = xs[(size_t)__ldcs(srt + e + 1) * (DIM / 4) + qoff];
        acc.x += r0.x + r1.x; acc.y += r0.y + r1.y;
        acc.z += r0.z + r1.z; acc.w += r0.w + r1.w;
    }
    if (e < end) {
        float4 r = xs[(size_t)__ldcs(srt + e) * (DIM / 4) + qoff];
        acc.x += r.x; acc.y += r.y; acc.z += r.z; acc.w += r.w;
    }
    int d = end - beg;
    float inv = 1.0f / (float)(d > 1 ? d : 1);
    float4 o;
    o.x = __uint_as_float(f2tf32(acc.x * inv));
    o.y = __uint_as_float(f2tf32(acc.y * inv));
    o.z = __uint_as_float(f2tf32(acc.z * inv));
    o.w = __uint_as_float(f2tf32(acc.w * inv));
    __stcs(reinterpret_cast<float4*>(aggout) + (size_t)v * (DIM / 4) + qoff, o);
}

// W[k][n] -> Wt[n][k], tf32(RNA)-rounded
__global__ void transpose_round_kernel(const float* __restrict__ W, float* __restrict__ Wt) {
    __shared__ float tile[32][33];
    int bx = blockIdx.x * 32, by = blockIdx.y * 32;
    int tx = threadIdx.x, ty = threadIdx.y;   // 32 x 8
    #pragma unroll
    for (int i = 0; i < 32; i += 8)
        tile[ty + i][tx] = W[(size_t)(by + ty + i) * DIM + bx + tx];
    __syncthreads();
    #pragma unroll
    for (int i = 0; i < 32; i += 8)
        Wt[(size_t)(bx + ty + i) * DIM + by + tx] = __uint_as_float(f2tf32(tile[tx][ty + i]));
}

// ---------------- cp.async + ldmatrix TF32 GEMM, BM=256 x BN=128 ----------------
// BK = 32 floats = 128B row = one SW128 atom. Chunk swizzle: c' = c ^ (row & 7).
// Per stage: A-half0 16KB + A-half1 16KB + B 16KB = 48KB; 3-stage = 144KB.
#define TILE_BYTES   16384
#define STAGE_BYTES  (3 * TILE_BYTES)
#define NSTAGE 3
#define GEMM_SMEM_DYN (NSTAGE * STAGE_BYTES)   // 147456 B

template <int CHUNKS>
__device__ __forceinline__ void gemm_body(
    int bm, int bn,
    const float* __restrict__ A0, const float* __restrict__ A1,
    const float* __restrict__ Wt0, const float* __restrict__ Wt1,
    const float* __restrict__ bias0, const float* __restrict__ bias1,
    float* __restrict__ C, int M, float* smem)
{
    const uint32_t smem_u32 = smem_to_u32(smem);

    const int t      = threadIdx.x;
    const int lane   = t & 31;
    const int warp   = t >> 5;
    const int warp_m = warp >> 2;   // 0..1 (within each 128-row half)
    const int warp_n = warp & 3;    // 0..3
    const int g      = lane >> 2;
    const int tid4   = lane & 3;
    const int lane7  = lane & 7;

    const int KT = 32 * CHUNKS;   // BK=32 tiles

    const int s_row = t >> 3;     // + it*32
    const int s_c   = t & 7;

    auto stage = [&](int kt, int buf) {
        const float* Asrc = (CHUNKS == 2 && kt >= 32) ? A1 : A0;
        const float* Wsrc = (CHUNKS == 2 && kt >= 32) ? Wt1 : Wt0;
        const int k0 = (kt & 31) * 32;                 // float offset
        const uint32_t base = smem_u32 + (uint32_t)buf * STAGE_BYTES;
        #pragma unroll
        for (int it = 0; it < 4; ++it) {
            int row = s_row + it * 32;                 // 0..127
            uint32_t dst = (uint32_t)(row * 128 + ((s_c ^ (row & 7)) * 16));
            // A half 0
            int gm0 = bm + row;
            int gm0c = (gm0 < M) ? gm0 : 0;
            cp_async16(base + dst, Asrc + (size_t)gm0c * DIM + k0 + s_c * 4,
                       (gm0 < M) ? 16u : 0u);
            // A half 1
            int gm1 = bm + 128 + row;
            int gm1c = (gm1 < M) ? gm1 : 0;
            cp_async16(base + TILE_BYTES + dst, Asrc + (size_t)gm1c * DIM + k0 + s_c * 4,
                       (gm1 < M) ? 16u : 0u);
            // B
            int gn = bn + row;
            cp_async16(base + 2 * TILE_BYTES + dst, Wsrc + (size_t)gn * DIM + k0 + s_c * 4, 16u);
        }
    };

    // ldmatrix address components (loop-invariant)
    uint32_t rowoff_a[4], rowoff_bp[2], cka[4], ckb[4];
    {
        int khia = lane >> 4;          // A: lanes 16-31 -> k-hi half
        int khib = (lane >> 3) & 1;    // B x4: matrix pair k halves
        int ntp  = lane >> 4;          // B x4: which n-subtile within pair
        #pragma unroll
        for (int mt = 0; mt < 4; mt++)
            rowoff_a[mt] = (uint32_t)((warp_m * 64 + mt * 16 + (lane & 15)) * 128);
        #pragma unroll
        for (int p = 0; p < 2; p++)
            rowoff_bp[p] = (uint32_t)((warp_n * 32 + (p * 2 + ntp) * 8 + lane7) * 128);
        #pragma unroll
        for (int k = 0; k < 4; k++) {
            cka[k] = (uint32_t)((((2 * k + khia) ^ lane7)) * 16);
            ckb[k] = (uint32_t)((((2 * k + khib) ^ lane7)) * 16);
        }
    }

    float c[2][4][4][4];
    #pragma unroll
    for (int h = 0; h < 2; h++)
        #pragma unroll
        for (int mt = 0; mt < 4; mt++)
            #pragma unroll
            for (int nt = 0; nt < 4; nt++)
                #pragma unroll
                for (int r = 0; r < 4; r++) c[h][mt][nt][r] = 0.f;

    auto compute = [&](int buf) {
        const uint32_t base = smem_u32 + (uint32_t)buf * STAGE_BYTES;
        const uint32_t bbase = base + 2 * TILE_BYTES;
        #pragma unroll
        for (int kstep = 0; kstep < 4; ++kstep) {
            uint32_t b[4][2];
            #pragma unroll
            for (int p = 0; p < 2; p++) {
                uint32_t bq[4];
                ldsm_x4(bq, bbase + rowoff_bp[p] + ckb[kstep]);
                b[2 * p][0] = bq[0]; b[2 * p][1] = bq[1];
                b[2 * p + 1][0] = bq[2]; b[2 * p + 1][1] = bq[3];
            }
            #pragma unroll
            for (int h = 0; h < 2; h++) {
                const uint32_t abase = base + (uint32_t)h * TILE_BYTES;
                #pragma unroll
                for (int mt = 0; mt < 4; mt++) {
                    uint32_t a[4];
                    ldsm_x4(a, abase + rowoff_a[mt] + cka[kstep]);
                    #pragma unroll
                    for (int nt = 0; nt < 4; nt++)
                        mma_tf32(c[h][mt][nt][0], c[h][mt][nt][1],
                                 c[h][mt][nt][2], c[h][mt][nt][3],
                                 a[0], a[1], a[2], a[3],
                                 b[nt][0], b[nt][1]);
                }
            }
        }
    };

    stage(0, 0); cp_async_commit();
    stage(1, 1); cp_async_commit();

    int buf = 0;
    for (int kt = 0; kt < KT; ++kt) {
        cp_async_wait<1>();
        __syncthreads();
        compute(buf);
        if (kt + 2 < KT) stage(kt + 2, (buf + 2) % NSTAGE);
        cp_async_commit();
        buf = (buf + 1) % NSTAGE;
    }

    // C stores evict-first (dead stream)
    #pragma unroll
    for (int h = 0; h < 2; h++) {
        #pragma unroll
        for (int mt = 0; mt < 4; mt++) {
            int r0 = bm + h * 128 + warp_m * 64 + mt * 16 + g;
            int r1 = r0 + 8;
            #pragma unroll
            for (int nt = 0; nt < 4; nt++) {
                int col = bn + warp_n * 32 + nt * 8 + tid4 * 2;
                float bv0 = bias0[col], bv1 = bias0[col + 1];
                if (CHUNKS == 2) { bv0 += bias1[col]; bv1 += bias1[col + 1]; }
                if (r0 < M) {
                    float* p = &C[(size_t)r0 * DIM + col];
                    __stcs(reinterpret_cast<float2*>(p),
                           make_float2(c[h][mt][nt][0] + bv0, c[h][mt][nt][1] + bv1));
                }
                if (r1 < M) {
                    float* p = &C[(size_t)r1 * DIM + col];
                    __stcs(reinterpret_cast<float2*>(p),
                           make_float2(c[h][mt][nt][2] + bv0, c[h][mt][nt][3] + bv1));
                }
            }
        }
    }
}

// combined GEMM launch: blocks [0, GEMM_BLOCKS) = prot (K=2048, dpi+ppi);
// blocks [GEMM_BLOCKS, 2*GEMM_BLOCKS) = ddi (K=1024).
__global__ __launch_bounds__(256) void gemm_combined_kernel(
    const float* __restrict__ A0, const float* __restrict__ A1,
    const float* __restrict__ Wt0, const float* __restrict__ Wt1,
    const float* __restrict__ bias0, const float* __restrict__ bias1,
    float* __restrict__ Cprot,
    const float* __restrict__ A2, const float* __restrict__ Wt2,
    const float* __restrict__ bias2, float* __restrict__ Cdrug, int M)
{
    extern __shared__ float smem[];
    if (blockIdx.x < GEMM_BLOCKS) {
        int bm = (blockIdx.x / GEMM_NBLKS) * 256;
        int bn = (blockIdx.x % GEMM_NBLKS) * 128;
        gemm_body<2>(bm, bn, A0, A1, Wt0, Wt1, bias0, bias1, Cprot, M, smem);
    } else {
        int b = blockIdx.x - GEMM_BLOCKS;
        int bm = (b / GEMM_NBLKS) * 256;
        int bn = (b % GEMM_NBLKS) * 128;
        gemm_body<1>(bm, bn, A2, nullptr, Wt2, nullptr, bias2, nullptr, Cdrug, M, smem);
    }
}

// ---------------- launch (single capture stream) ----------------
static void run_sort(int rel, const int* src, const int* dst)
{
    zero_deg_kernel<<<(N_NODE + 255) / 256, 256>>>(rel);
    hist_kernel<<<(N_EDGE + 255) / 256, 256>>>(rel, dst);
    scan_block_kernel<<<NBLK_SCAN, 1024>>>(rel);
    scan_add_kernel<<<NBLK_SCAN, 1024>>>(rel);
    scatter_kernel<<<(N_EDGE + 255) / 256, 256>>>(rel, src, dst);
}

extern "C" void kernel_launch(void* const* d_in, const int* in_sizes, int n_in,
                              void* d_out, int out_size)
{
    const float* x_drug = (const float*)d_in[0];
    const float* x_prot = (const float*)d_in[1];
    const float* W_ddi  = (const float*)d_in[2];
    const float* b_ddi  = (const float*)d_in[3];
    const float* W_dpi  = (const float*)d_in[4];
    const float* b_dpi  = (const float*)d_in[5];
    const float* W_ppi  = (const float*)d_in[6];
    const float* b_ppi  = (const float*)d_in[7];
    const int* src_ddi  = (const int*)d_in[8];
    const int* dst_ddi  = (const int*)d_in[9];
    const int* src_dpi  = (const int*)d_in[10];
    const int* dst_dpi  = (const int*)d_in[11];
    const int* src_ppi  = (const int*)d_in[12];
    const int* dst_ppi  = (const int*)d_in[13];

    float* out_drug = (float*)d_out;
    float* out_prot = out_drug + (size_t)N_NODE * DIM;

    float* agg0; cudaGetSymbolAddress((void**)&agg0, g_agg0);   // dpi
    float* agg1; cudaGetSymbolAddress((void**)&agg1, g_agg1);   // ppi
    float* agg2; cudaGetSymbolAddress((void**)&agg2, g_agg2);   // ddi
    float* wt0;  cudaGetSymbolAddress((void**)&wt0,  g_wt0);
    float* wt1;  cudaGetSymbolAddress((void**)&wt1,  g_wt1);
    float* wt2;  cudaGetSymbolAddress((void**)&wt2,  g_wt2);

    cudaFuncSetAttribute(gemm_combined_kernel,
                         cudaFuncAttributeMaxDynamicSharedMemorySize, GEMM_SMEM_DYN);

    dim3 tgrid(32, 32), tblk(32, 8);

    // ---- all sorts up front ----
    run_sort(0, src_dpi, dst_dpi);
    run_sort(1, src_ppi, dst_ppi);
    run_sort(2, src_ddi, dst_ddi);

    // ---- weight transposes ----
    transpose_round_kernel<<<tgrid, tblk>>>(W_dpi, wt0);
    transpose_round_kernel<<<tgrid, tblk>>>(W_ppi, wt1);
    transpose_round_kernel<<<tgrid, tblk>>>(W_ddi, wt2);

    // ---- aggregates: interleave dpi+ddi (both gather x_drug), then ppi ----
    for (int c = 0; c < DCHUNKS; ++c) {
        aggregate_chunk_kernel<<<N_NODE, 128>>>(0, c, x_drug, agg0);
        aggregate_chunk_kernel<<<N_NODE, 128>>>(2, c, x_drug, agg2);
    }
    for (int c = 0; c < DCHUNKS; ++c)
        aggregate_chunk_kernel<<<N_NODE, 128>>>(1, c, x_prot, agg1);

    // ---- single combined GEMM launch: prot (K=2048) + ddi (K=1024) ----
    gemm_combined_kernel<<<2 * GEMM_BLOCKS, 256, GEMM_SMEM_DYN>>>(
        agg0, agg1, wt0, wt1, b_dpi, b_ppi, out_prot,
        agg2, wt2, b_ddi, out_drug, N_NODE);
}

// round 16
// speedup vs baseline: 1.4020x; 1.0198x over previous
#include <cuda_runtime.h>
#include <cuda_bf16.h>
#include <cstdint>

// Problem constants
#define N_NODE 40000
#define N_EDGE 320000
#define DIM    1024
#define NBLK_SCAN 40            // ceil(40000/1024)
#define DCHUNKS 2               // 2 x 512-float slices

#define GEMM_MBLKS ((N_NODE + 255) / 256)     // 157 (BM=256)
#define GEMM_NBLKS (DIM / 128)                // 8
#define GEMM_BLOCKS (GEMM_MBLKS * GEMM_NBLKS) // 1256

// ---------------- device scratch (no cudaMalloc allowed) ----------------
__device__ int   g_deg[3 * N_NODE];
__device__ int   g_offs[3 * (N_NODE + 1)];
__device__ int   g_cursor[3 * N_NODE];
__device__ int   g_sorted_src[3 * N_EDGE];
__device__ int   g_bsum[3 * NBLK_SCAN];
__device__ float g_agg0[(size_t)N_NODE * DIM];   // dpi
__device__ float g_agg1[(size_t)N_NODE * DIM];   // ppi
__device__ float g_agg2[(size_t)N_NODE * DIM];   // ddi
__device__ float g_wt0[(size_t)DIM * DIM];
__device__ float g_wt1[(size_t)DIM * DIM];
__device__ float g_wt2[(size_t)DIM * DIM];

// ---------------- helpers ----------------
__device__ __forceinline__ uint32_t f2tf32(float x) {
    uint32_t r;
    asm("cvt.rna.tf32.f32 %0, %1;" : "=r"(r) : "f"(x));
    return r;
}

__device__ __forceinline__ uint32_t smem_to_u32(const void* smem_ptr) {
    uint32_t addr;
    asm("{ .reg .u64 tmp; cvta.to.shared.u64 tmp, %1; cvt.u32.u64 %0, tmp; }"
        : "=r"(addr) : "l"(smem_ptr));
    return addr;
}

__device__ __forceinline__ void cp_async16(uint32_t smem_addr, const void* gptr, uint32_t src_size) {
    asm volatile("cp.async.ca.shared.global [%0], [%1], 16, %2;"
                 :: "r"(smem_addr), "l"(gptr), "r"(src_size));
}
__device__ __forceinline__ void cp_async_commit() {
    asm volatile("cp.async.commit_group;" ::: "memory");
}
template <int N>
__device__ __forceinline__ void cp_async_wait() {
    asm volatile("cp.async.wait_group %0;" :: "n"(N) : "memory");
}

__device__ __forceinline__ void ldsm_x4(uint32_t* r, uint32_t addr) {
    asm volatile("ldmatrix.sync.aligned.m8n8.x4.shared.b16 {%0,%1,%2,%3}, [%4];"
                 : "=r"(r[0]), "=r"(r[1]), "=r"(r[2]), "=r"(r[3]) : "r"(addr));
}

__device__ __forceinline__ void mma_tf32(float& c0, float& c1, float& c2, float& c3,
                                         uint32_t a0, uint32_t a1, uint32_t a2, uint32_t a3,
                                         uint32_t b0, uint32_t b1) {
    asm volatile(
        "mma.sync.aligned.m16n8k8.row.col.f32.tf32.tf32.f32 "
        "{%0,%1,%2,%3}, {%4,%5,%6,%7}, {%8,%9}, {%0,%1,%2,%3};"
        : "+f"(c0), "+f"(c1), "+f"(c2), "+f"(c3)
        : "r"(a0), "r"(a1), "r"(a2), "r"(a3), "r"(b0), "r"(b1));
}

// ---------------- batched sort-by-dst pipeline (all 3 relations per launch) ----------------
__global__ void zero_deg_all_kernel() {
    int i = blockIdx.x * blockDim.x + threadIdx.x;
    if (i < 3 * N_NODE) g_deg[i] = 0;
}

__global__ void hist_all_kernel(const int* __restrict__ d0, const int* __restrict__ d1,
                                const int* __restrict__ d2) {
    int rel = blockIdx.y;
    const int* dst = (rel == 0) ? d0 : (rel == 1) ? d1 : d2;
    int i = blockIdx.x * blockDim.x + threadIdx.x;
    if (i < N_EDGE) atomicAdd(&g_deg[rel * N_NODE + __ldcs(dst + i)], 1);
}

__global__ void scan_block_all_kernel() {
    int rel = blockIdx.y;
    int t = threadIdx.x;
    int lane = t & 31, wid = t >> 5;
    int gidx = blockIdx.x * 1024 + t;
    int v = (gidx < N_NODE) ? g_deg[rel * N_NODE + gidx] : 0;
    int x = v;
    #pragma unroll
    for (int o = 1; o < 32; o <<= 1) {
        int y = __shfl_up_sync(0xFFFFFFFFu, x, o);
        if (lane >= o) x += y;
    }
    __shared__ int wsum[32];
    if (lane == 31) wsum[wid] = x;
    __syncthreads();
    if (wid == 0) {
        int w = wsum[lane];
        #pragma unroll
        for (int o = 1; o < 32; o <<= 1) {
            int y = __shfl_up_sync(0xFFFFFFFFu, w, o);
            if (lane >= o) w += y;
        }
        wsum[lane] = w;
    }
    __syncthreads();
    int incl = x + (wid ? wsum[wid - 1] : 0);
    if (gidx < N_NODE) g_offs[rel * (N_NODE + 1) + gidx] = incl - v;
    __syncthreads();
    if (t == 1023) g_bsum[rel * NBLK_SCAN + blockIdx.x] = wsum[31];
}

__global__ void scan_add_all_kernel() {
    int rel = blockIdx.y;
    __shared__ int sh[NBLK_SCAN];
    int t = threadIdx.x;
    if (t < NBLK_SCAN) sh[t] = g_bsum[rel * NBLK_SCAN + t];
    __syncthreads();
    int boff = 0;
    for (int b = 0; b < blockIdx.x; ++b) boff += sh[b];
    int gidx = blockIdx.x * 1024 + t;
    if (gidx < N_NODE) {
        int o = g_offs[rel * (N_NODE + 1) + gidx] + boff;
        g_offs[rel * (N_NODE + 1) + gidx] = o;
        g_cursor[rel * N_NODE + gidx] = o;
    }
    if (blockIdx.x == 0 && t == 0)
        g_offs[rel * (N_NODE + 1) + N_NODE] = N_EDGE;
}

__global__ void scatter_all_kernel(const int* __restrict__ s0, const int* __restrict__ d0,
                                   const int* __restrict__ s1, const int* __restrict__ d1,
                                   const int* __restrict__ s2, const int* __restrict__ d2) {
    int rel = blockIdx.y;
    const int* src = (rel == 0) ? s0 : (rel == 1) ? s1 : s2;
    const int* dst = (rel == 0) ? d0 : (rel == 1) ? d1 : d2;
    int i = blockIdx.x * blockDim.x + threadIdx.x;
    if (i < N_EDGE) {
        int pos = atomicAdd(&g_cursor[rel * N_NODE + __ldcs(dst + i)], 1);
        __stcs(&g_sorted_src[rel * N_EDGE + pos], __ldcs(src + i));
    }
}

// ---------------- merged aggregate: all 6 passes in one launch ----------------
// Block decode (scheduling ~in blockIdx order preserves the proven interleave):
//   blocks [0, 4N): chunk c = i/(2N); within chunk, even->dpi(rel0), odd->ddi(rel2),
//                   both gathering x_drug (L2 slice shared at per-node grain).
//   blocks [4N, 6N): ppi (rel1), chunk = (i-4N)/N, gathering x_prot.
__global__ void aggregate_all_kernel(const float* __restrict__ x_drug,
                                     const float* __restrict__ x_prot,
                                     float* __restrict__ agg0,
                                     float* __restrict__ agg1,
                                     float* __restrict__ agg2) {
    int i = blockIdx.x;
    int rel, v, dchunk;
    const float* xsrc;
    float* aggout;
    if (i < 4 * N_NODE) {
        dchunk = i / (2 * N_NODE);
        int j = i % (2 * N_NODE);
        v = j >> 1;
        if (j & 1) { rel = 2; aggout = agg2; }
        else       { rel = 0; aggout = agg0; }
        xsrc = x_drug;
    } else {
        int j = i - 4 * N_NODE;
        dchunk = j / N_NODE;
        v = j % N_NODE;
        rel = 1; xsrc = x_prot; aggout = agg1;
    }

    const int* offs = g_offs + rel * (N_NODE + 1);
    const int* srt  = g_sorted_src + rel * N_EDGE;
    int beg = offs[v];
    int end = offs[v + 1];
    int t = threadIdx.x;                       // 0..127
    const int qoff = dchunk * 128 + t;

    float4 acc = make_float4(0.f, 0.f, 0.f, 0.f);
    const float4* xs = reinterpret_cast<const float4*>(xsrc);
    int e = beg;
    for (; e + 7 < end; e += 8) {
        float4 r[8];
        #pragma unroll
        for (int j = 0; j < 8; j++)
            r[j] = xs[(size_t)__ldcs(srt + e + j) * (DIM / 4) + qoff];
        #pragma unroll
        for (int j = 0; j < 8; j++) {
            acc.x += r[j].x; acc.y += r[j].y; acc.z += r[j].z; acc.w += r[j].w;
        }
    }
    for (; e + 1 < end; e += 2) {
        float4 r0 = xs[(size_t)__ldcs(srt + e) * (DIM / 4) + qoff];
        float4 r1 = xs[(size_t)__ldcs(srt + e + 1) * (DIM / 4) + qoff];
        acc.x += r0.x + r1.x; acc.y += r0.y + r1.y;
        acc.z += r0.z + r1.z; acc.w += r0.w + r1.w;
    }
    if (e < end) {
        float4 r = xs[(size_t)__ldcs(srt + e) * (DIM / 4) + qoff];
        acc.x += r.x; acc.y += r.y; acc.z += r.z; acc.w += r.w;
    }
    int d = end - beg;
    float inv = 1.0f / (float)(d > 1 ? d : 1);
    float4 o;
    o.x = __uint_as_float(f2tf32(acc.x * inv));
    o.y = __uint_as_float(f2tf32(acc.y * inv));
    o.z = __uint_as_float(f2tf32(acc.z * inv));
    o.w = __uint_as_float(f2tf32(acc.w * inv));
    __stcs(reinterpret_cast<float4*>(aggout) + (size_t)v * (DIM / 4) + qoff, o);
}

// W[k][n] -> Wt[n][k], tf32(RNA)-rounded; batched over 3 weights via blockIdx.z
__global__ void transpose_round_all_kernel(const float* __restrict__ W0, float* __restrict__ Wt0,
                                           const float* __restrict__ W1, float* __restrict__ Wt1,
                                           const float* __restrict__ W2, float* __restrict__ Wt2) {
    int rel = blockIdx.z;
    const float* W  = (rel == 0) ? W0 : (rel == 1) ? W1 : W2;
    float*       Wt = (rel == 0) ? Wt0 : (rel == 1) ? Wt1 : Wt2;
    __shared__ float tile[32][33];
    int bx = blockIdx.x * 32, by = blockIdx.y * 32;
    int tx = threadIdx.x, ty = threadIdx.y;   // 32 x 8
    #pragma unroll
    for (int i = 0; i < 32; i += 8)
        tile[ty + i][tx] = W[(size_t)(by + ty + i) * DIM + bx + tx];
    __syncthreads();
    #pragma unroll
    for (int i = 0; i < 32; i += 8)
        Wt[(size_t)(bx + ty + i) * DIM + by + tx] = __uint_as_float(f2tf32(tile[tx][ty + i]));
}

// ---------------- cp.async + ldmatrix TF32 GEMM, BM=256 x BN=128 ----------------
// BK = 32 floats = 128B row = one SW128 atom. Chunk swizzle: c' = c ^ (row & 7).
// Per stage: A-half0 16KB + A-half1 16KB + B 16KB = 48KB; 3-stage = 144KB.
#define TILE_BYTES   16384
#define STAGE_BYTES  (3 * TILE_BYTES)
#define NSTAGE 3
#define GEMM_SMEM_DYN (NSTAGE * STAGE_BYTES)   // 147456 B

template <int CHUNKS>
__device__ __forceinline__ void gemm_body(
    int bm, int bn,
    const float* __restrict__ A0, const float* __restrict__ A1,
    const float* __restrict__ Wt0, const float* __restrict__ Wt1,
    const float* __restrict__ bias0, const float* __restrict__ bias1,
    float* __restrict__ C, int M, float* smem)
{
    const uint32_t smem_u32 = smem_to_u32(smem);

    const int t      = threadIdx.x;
    const int lane   = t & 31;
    const int warp   = t >> 5;
    const int warp_m = warp >> 2;   // 0..1 (within each 128-row half)
    const int warp_n = warp & 3;    // 0..3
    const int g      = lane >> 2;
    const int tid4   = lane & 3;
    const int lane7  = lane & 7;

    const int KT = 32 * CHUNKS;   // BK=32 tiles

    const int s_row = t >> 3;     // + it*32
    const int s_c   = t & 7;

    auto stage = [&](int kt, int buf) {
        const float* Asrc = (CHUNKS == 2 && kt >= 32) ? A1 : A0;
        const float* Wsrc = (CHUNKS == 2 && kt >= 32) ? Wt1 : Wt0;
        const int k0 = (kt & 31) * 32;                 // float offset
        const uint32_t base = smem_u32 + (uint32_t)buf * STAGE_BYTES;
        #pragma unroll
        for (int it = 0; it < 4; ++it) {
            int row = s_row + it * 32;                 // 0..127
            uint32_t dst = (uint32_t)(row * 128 + ((s_c ^ (row & 7)) * 16));
            // A half 0
            int gm0 = bm + row;
            int gm0c = (gm0 < M) ? gm0 : 0;
            cp_async16(base + dst, Asrc + (size_t)gm0c * DIM + k0 + s_c * 4,
                       (gm0 < M) ? 16u : 0u);
            // A half 1
            int gm1 = bm + 128 + row;
            int gm1c = (gm1 < M) ? gm1 : 0;
            cp_async16(base + TILE_BYTES + dst, Asrc + (size_t)gm1c * DIM + k0 + s_c * 4,
                       (gm1 < M) ? 16u : 0u);
            // B
            int gn = bn + row;
            cp_async16(base + 2 * TILE_BYTES + dst, Wsrc + (size_t)gn * DIM + k0 + s_c * 4, 16u);
        }
    };

    // ldmatrix address components (loop-invariant)
    uint32_t rowoff_a[4], rowoff_bp[2], cka[4], ckb[4];
    {
        int khia = lane >> 4;          // A: lanes 16-31 -> k-hi half
        int khib = (lane >> 3) & 1;    // B x4: matrix pair k halves
        int ntp  = lane >> 4;          // B x4: which n-subtile within pair
        #pragma unroll
        for (int mt = 0; mt < 4; mt++)
            rowoff_a[mt] = (uint32_t)((warp_m * 64 + mt * 16 + (lane & 15)) * 128);
        #pragma unroll
        for (int p = 0; p < 2; p++)
            rowoff_bp[p] = (uint32_t)((warp_n * 32 + (p * 2 + ntp) * 8 + lane7) * 128);
        #pragma unroll
        for (int k = 0; k < 4; k++) {
            cka[k] = (uint32_t)((((2 * k + khia) ^ lane7)) * 16);
            ckb[k] = (uint32_t)((((2 * k + khib) ^ lane7)) * 16);
        }
    }

    float c[2][4][4][4];
    #pragma unroll
    for (int h = 0; h < 2; h++)
        #pragma unroll
        for (int mt = 0; mt < 4; mt++)
            #pragma unroll
            for (int nt = 0; nt < 4; nt++)
                #pragma unroll
                for (int r = 0; r < 4; r++) c[h][mt][nt][r] = 0.f;

    auto compute = [&](int buf) {
        const uint32_t base = smem_u32 + (uint32_t)buf * STAGE_BYTES;
        const uint32_t bbase = base + 2 * TILE_BYTES;
        #pragma unroll
        for (int kstep = 0; kstep < 4; ++kstep) {
            uint32_t b[4][2];
            #pragma unroll
            for (int p = 0; p < 2; p++) {
                uint32_t bq[4];
                ldsm_x4(bq, bbase + rowoff_bp[p] + ckb[kstep]);
                b[2 * p][0] = bq[0]; b[2 * p][1] = bq[1];
                b[2 * p + 1][0] = bq[2]; b[2 * p + 1][1] = bq[3];
            }
            #pragma unroll
            for (int h = 0; h < 2; h++) {
                const uint32_t abase = base + (uint32_t)h * TILE_BYTES;
                #pragma unroll
                for (int mt = 0; mt < 4; mt++) {
                    uint32_t a[4];
                    ldsm_x4(a, abase + rowoff_a[mt] + cka[kstep]);
                    #pragma unroll
                    for (int nt = 0; nt < 4; nt++)
                        mma_tf32(c[h][mt][nt][0], c[h][mt][nt][1],
                                 c[h][mt][nt][2], c[h][mt][nt][3],
                                 a[0], a[1], a[2], a[3],
                                 b[nt][0], b[nt][1]);
                }
            }
        }
    };

    stage(0, 0); cp_async_commit();
    stage(1, 1); cp_async_commit();

    int buf = 0;
    for (int kt = 0; kt < KT; ++kt) {
        cp_async_wait<1>();
        __syncthreads();
        compute(buf);
        if (kt + 2 < KT) stage(kt + 2, (buf + 2) % NSTAGE);
        cp_async_commit();
        buf = (buf + 1) % NSTAGE;
    }

    // C stores evict-first (dead stream)
    #pragma unroll
    for (int h = 0; h < 2; h++) {
        #pragma unroll
        for (int mt = 0; mt < 4; mt++) {
            int r0 = bm + h * 128 + warp_m * 64 + mt * 16 + g;
            int r1 = r0 + 8;
            #pragma unroll
            for (int nt = 0; nt < 4; nt++) {
                int col = bn + warp_n * 32 + nt * 8 + tid4 * 2;
                float bv0 = bias0[col], bv1 = bias0[col + 1];
                if (CHUNKS == 2) { bv0 += bias1[col]; bv1 += bias1[col + 1]; }
                if (r0 < M) {
                    float* p = &C[(size_t)r0 * DIM + col];
                    __stcs(reinterpret_cast<float2*>(p),
                           make_float2(c[h][mt][nt][0] + bv0, c[h][mt][nt][1] + bv1));
                }
                if (r1 < M) {
                    float* p = &C[(size_t)r1 * DIM + col];
                    __stcs(reinterpret_cast<float2*>(p),
                           make_float2(c[h][mt][nt][2] + bv0, c[h][mt][nt][3] + bv1));
                }
            }
        }
    }
}

// combined GEMM launch: blocks [0, GEMM_BLOCKS) = prot (K=2048, dpi+ppi);
// blocks [GEMM_BLOCKS, 2*GEMM_BLOCKS) = ddi (K=1024).
__global__ __launch_bounds__(256) void gemm_combined_kernel(
    const float* __restrict__ A0, const float* __restrict__ A1,
    const float* __restrict__ Wt0, const float* __restrict__ Wt1,
    const float* __restrict__ bias0, const float* __restrict__ bias1,
    float* __restrict__ Cprot,
    const float* __restrict__ A2, const float* __restrict__ Wt2,
    const float* __restrict__ bias2, float* __restrict__ Cdrug, int M)
{
    extern __shared__ float smem[];
    if (blockIdx.x < GEMM_BLOCKS) {
        int bm = (blockIdx.x / GEMM_NBLKS) * 256;
        int bn = (blockIdx.x % GEMM_NBLKS) * 128;
        gemm_body<2>(bm, bn, A0, A1, Wt0, Wt1, bias0, bias1, Cprot, M, smem);
    } else {
        int b = blockIdx.x - GEMM_BLOCKS;
        int bm = (b / GEMM_NBLKS) * 256;
        int bn = (b % GEMM_NBLKS) * 128;
        gemm_body<1>(bm, bn, A2, nullptr, Wt2, nullptr, bias2, nullptr, Cdrug, M, smem);
    }
}

// ---------------- launch (single capture stream) ----------------
extern "C" void kernel_launch(void* const* d_in, const int* in_sizes, int n_in,
                              void* d_out, int out_size)
{
    const float* x_drug = (const float*)d_in[0];
    const float* x_prot = (const float*)d_in[1];
    const float* W_ddi  = (const float*)d_in[2];
    const float* b_ddi  = (const float*)d_in[3];
    const float* W_dpi  = (const float*)d_in[4];
    const float* b_dpi  = (const float*)d_in[5];
    const float* W_ppi  = (const float*)d_in[6];
    const float* b_ppi  = (const float*)d_in[7];
    const int* src_ddi  = (const int*)d_in[8];
    const int* dst_ddi  = (const int*)d_in[9];
    const int* src_dpi  = (const int*)d_in[10];
    const int* dst_dpi  = (const int*)d_in[11];
    const int* src_ppi  = (const int*)d_in[12];
    const int* dst_ppi  = (const int*)d_in[13];

    float* out_drug = (float*)d_out;
    float* out_prot = out_drug + (size_t)N_NODE * DIM;

    float* agg0; cudaGetSymbolAddress((void**)&agg0, g_agg0);   // dpi
    float* agg1; cudaGetSymbolAddress((void**)&agg1, g_agg1);   // ppi
    float* agg2; cudaGetSymbolAddress((void**)&agg2, g_agg2);   // ddi
    float* wt0;  cudaGetSymbolAddress((void**)&wt0,  g_wt0);
    float* wt1;  cudaGetSymbolAddress((void**)&wt1,  g_wt1);
    float* wt2;  cudaGetSymbolAddress((void**)&wt2,  g_wt2);

    cudaFuncSetAttribute(gemm_combined_kernel,
                         cudaFuncAttributeMaxDynamicSharedMemorySize, GEMM_SMEM_DYN);

    // ---- batched sorts: rel 0 = dpi, 1 = ppi, 2 = ddi ----
    zero_deg_all_kernel<<<(3 * N_NODE + 255) / 256, 256>>>();
    {
        dim3 g((N_EDGE + 255) / 256, 3);
        hist_all_kernel<<<g, 256>>>(dst_dpi, dst_ppi, dst_ddi);
    }
    {
        dim3 g(NBLK_SCAN, 3);
        scan_block_all_kernel<<<g, 1024>>>();
        scan_add_all_kernel<<<g, 1024>>>();
    }
    {
        dim3 g((N_EDGE + 255) / 256, 3);
        scatter_all_kernel<<<g, 256>>>(src_dpi, dst_dpi, src_ppi, dst_ppi, src_ddi, dst_ddi);
    }

    // ---- batched weight transposes ----
    {
        dim3 g(32, 32, 3), b(32, 8);
        transpose_round_all_kernel<<<g, b>>>(W_dpi, wt0, W_ppi, wt1, W_ddi, wt2);
    }

    // ---- merged aggregate launch (all 6 passes; dpi/ddi pair-interleaved, then ppi) ----
    aggregate_all_kernel<<<6 * N_NODE, 128>>>(x_drug, x_prot, agg0, agg1, agg2);

    // ---- single combined GEMM launch: prot (K=2048) + ddi (K=1024) ----
    gemm_combined_kernel<<<2 * GEMM_BLOCKS, 256, GEMM_SMEM_DYN>>>(
        agg0, agg1, wt0, wt1, b_dpi, b_ppi, out_prot,
        agg2, wt2, b_ddi, out_drug, N_NODE);
}

// round 17
// speedup vs baseline: 2.2277x; 1.5889x over previous
#include <cuda_runtime.h>
#include <cuda_fp16.h>
#include <cstdint>

// Problem constants
#define N_NODE 40000
#define N_EDGE 320000
#define DIM    1024
#define NBLK_SCAN 40            // ceil(40000/1024)
#define DCHUNKS 2               // 2 x 512-half slices

#define GEMM_MBLKS ((N_NODE + 255) / 256)     // 157 (BM=256)
#define GEMM_NBLKS (DIM / 128)                // 8
#define GEMM_BLOCKS (GEMM_MBLKS * GEMM_NBLKS) // 1256

// ---------------- device scratch (no cudaMalloc allowed) ----------------
__device__ int    g_deg[3 * N_NODE];
__device__ int    g_offs[3 * (N_NODE + 1)];
__device__ int    g_cursor[3 * N_NODE];
__device__ int    g_sorted_src[3 * N_EDGE];
__device__ int    g_bsum[3 * NBLK_SCAN];
__device__ __half g_xh_drug[(size_t)N_NODE * DIM];   // fp16 copy of x_drug
__device__ __half g_xh_prot[(size_t)N_NODE * DIM];   // fp16 copy of x_prot
__device__ __half g_agg0[(size_t)N_NODE * DIM];      // dpi (fp16)
__device__ __half g_agg1[(size_t)N_NODE * DIM];      // ppi
__device__ __half g_agg2[(size_t)N_NODE * DIM];      // ddi
__device__ __half g_wt0[(size_t)DIM * DIM];          // W^T fp16
__device__ __half g_wt1[(size_t)DIM * DIM];
__device__ __half g_wt2[(size_t)DIM * DIM];

// ---------------- helpers ----------------
__device__ __forceinline__ uint32_t smem_to_u32(const void* smem_ptr) {
    uint32_t addr;
    asm("{ .reg .u64 tmp; cvta.to.shared.u64 tmp, %1; cvt.u32.u64 %0, tmp; }"
        : "=r"(addr) : "l"(smem_ptr));
    return addr;
}

__device__ __forceinline__ void cp_async16(uint32_t smem_addr, const void* gptr, uint32_t src_size) {
    asm volatile("cp.async.ca.shared.global [%0], [%1], 16, %2;"
                 :: "r"(smem_addr), "l"(gptr), "r"(src_size));
}
__device__ __forceinline__ void cp_async_commit() {
    asm volatile("cp.async.commit_group;" ::: "memory");
}
template <int N>
__device__ __forceinline__ void cp_async_wait() {
    asm volatile("cp.async.wait_group %0;" :: "n"(N) : "memory");
}

__device__ __forceinline__ void ldsm_x4(uint32_t* r, uint32_t addr) {
    asm volatile("ldmatrix.sync.aligned.m8n8.x4.shared.b16 {%0,%1,%2,%3}, [%4];"
                 : "=r"(r[0]), "=r"(r[1]), "=r"(r[2]), "=r"(r[3]) : "r"(addr));
}

// fp16 MMA, fp32 accumulate: m16n8k16
__device__ __forceinline__ void mma_f16(float& c0, float& c1, float& c2, float& c3,
                                        uint32_t a0, uint32_t a1, uint32_t a2, uint32_t a3,
                                        uint32_t b0, uint32_t b1) {
    asm volatile(
        "mma.sync.aligned.m16n8k16.row.col.f32.f16.f16.f32 "
        "{%0,%1,%2,%3}, {%4,%5,%6,%7}, {%8,%9}, {%0,%1,%2,%3};"
        : "+f"(c0), "+f"(c1), "+f"(c2), "+f"(c3)
        : "r"(a0), "r"(a1), "r"(a2), "r"(a3), "r"(b0), "r"(b1));
}

// ---------------- fp32 -> fp16 conversion of inputs ----------------
__global__ void convert_x_kernel(const float4* __restrict__ xd, const float4* __restrict__ xp,
                                 uint2* __restrict__ xhd, uint2* __restrict__ xhp) {
    const float4* src = blockIdx.y ? xp : xd;
    uint2* dst = blockIdx.y ? xhp : xhd;
    size_t i = (size_t)blockIdx.x * blockDim.x + threadIdx.x;
    if (i < (size_t)N_NODE * DIM / 4) {
        float4 v = src[i];
        __half2 lo = __floats2half2_rn(v.x, v.y);
        __half2 hi = __floats2half2_rn(v.z, v.w);
        uint2 o;
        o.x = *reinterpret_cast<uint32_t*>(&lo);
        o.y = *reinterpret_cast<uint32_t*>(&hi);
        dst[i] = o;
    }
}

// ---------------- batched sort-by-dst pipeline ----------------
__global__ void zero_deg_all_kernel() {
    int i = blockIdx.x * blockDim.x + threadIdx.x;
    if (i < 3 * N_NODE) g_deg[i] = 0;
}

__global__ void hist_all_kernel(const int* __restrict__ d0, const int* __restrict__ d1,
                                const int* __restrict__ d2) {
    int rel = blockIdx.y;
    const int* dst = (rel == 0) ? d0 : (rel == 1) ? d1 : d2;
    int i = blockIdx.x * blockDim.x + threadIdx.x;
    if (i < N_EDGE) atomicAdd(&g_deg[rel * N_NODE + __ldcs(dst + i)], 1);
}

__global__ void scan_block_all_kernel() {
    int rel = blockIdx.y;
    int t = threadIdx.x;
    int lane = t & 31, wid = t >> 5;
    int gidx = blockIdx.x * 1024 + t;
    int v = (gidx < N_NODE) ? g_deg[rel * N_NODE + gidx] : 0;
    int x = v;
    #pragma unroll
    for (int o = 1; o < 32; o <<= 1) {
        int y = __shfl_up_sync(0xFFFFFFFFu, x, o);
        if (lane >= o) x += y;
    }
    __shared__ int wsum[32];
    if (lane == 31) wsum[wid] = x;
    __syncthreads();
    if (wid == 0) {
        int w = wsum[lane];
        #pragma unroll
        for (int o = 1; o < 32; o <<= 1) {
            int y = __shfl_up_sync(0xFFFFFFFFu, w, o);
            if (lane >= o) w += y;
        }
        wsum[lane] = w;
    }
    __syncthreads();
    int incl = x + (wid ? wsum[wid - 1] : 0);
    if (gidx < N_NODE) g_offs[rel * (N_NODE + 1) + gidx] = incl - v;
    __syncthreads();
    if (t == 1023) g_bsum[rel * NBLK_SCAN + blockIdx.x] = wsum[31];
}

__global__ void scan_add_all_kernel() {
    int rel = blockIdx.y;
    __shared__ int sh[NBLK_SCAN];
    int t = threadIdx.x;
    if (t < NBLK_SCAN) sh[t] = g_bsum[rel * NBLK_SCAN + t];
    __syncthreads();
    int boff = 0;
    for (int b = 0; b < blockIdx.x; ++b) boff += sh[b];
    int gidx = blockIdx.x * 1024 + t;
    if (gidx < N_NODE) {
        int o = g_offs[rel * (N_NODE + 1) + gidx] + boff;
        g_offs[rel * (N_NODE + 1) + gidx] = o;
        g_cursor[rel * N_NODE + gidx] = o;
    }
    if (blockIdx.x == 0 && t == 0)
        g_offs[rel * (N_NODE + 1) + N_NODE] = N_EDGE;
}

__global__ void scatter_all_kernel(const int* __restrict__ s0, const int* __restrict__ d0,
                                   const int* __restrict__ s1, const int* __restrict__ d1,
                                   const int* __restrict__ s2, const int* __restrict__ d2) {
    int rel = blockIdx.y;
    const int* src = (rel == 0) ? s0 : (rel == 1) ? s1 : s2;
    const int* dst = (rel == 0) ? d0 : (rel == 1) ? d1 : d2;
    int i = blockIdx.x * blockDim.x + threadIdx.x;
    if (i < N_EDGE) {
        int pos = atomicAdd(&g_cursor[rel * N_NODE + __ldcs(dst + i)], 1);
        __stcs(&g_sorted_src[rel * N_EDGE + pos], __ldcs(src + i));
    }
}

// ---------------- merged fp16 aggregate: all 6 passes in one launch ----------------
// blocks [0, 4N): chunk = i/(2N); even->dpi(rel0), odd->ddi(rel2), gather xh_drug.
// blocks [4N, 6N): ppi (rel1), gather xh_prot. Thread handles 4 halfs (8B).
__global__ void aggregate_all_kernel() {
    int i = blockIdx.x;
    int rel, v, dchunk;
    const __half* xsrc;
    __half* aggout;
    if (i < 4 * N_NODE) {
        dchunk = i / (2 * N_NODE);
        int j = i % (2 * N_NODE);
        v = j >> 1;
        if (j & 1) { rel = 2; aggout = g_agg2; }
        else       { rel = 0; aggout = g_agg0; }
        xsrc = g_xh_drug;
    } else {
        int j = i - 4 * N_NODE;
        dchunk = j / N_NODE;
        v = j % N_NODE;
        rel = 1; xsrc = g_xh_prot; aggout = g_agg1;
    }

    const int* offs = g_offs + rel * (N_NODE + 1);
    const int* srt  = g_sorted_src + rel * N_EDGE;
    int beg = offs[v];
    int end = offs[v + 1];
    int t = threadIdx.x;                       // 0..127
    const int qoff = dchunk * 128 + t;         // index in 4-half (8B) units

    float4 acc = make_float4(0.f, 0.f, 0.f, 0.f);
    const uint2* xs = reinterpret_cast<const uint2*>(xsrc);
    auto addv = [&](uint2 raw) {
        __half2 lo = *reinterpret_cast<__half2*>(&raw.x);
        __half2 hi = *reinterpret_cast<__half2*>(&raw.y);
        float2 flo = __half22float2(lo);
        float2 fhi = __half22float2(hi);
        acc.x += flo.x; acc.y += flo.y; acc.z += fhi.x; acc.w += fhi.y;
    };
    int e = beg;
    for (; e + 7 < end; e += 8) {
        uint2 r[8];
        #pragma unroll
        for (int j = 0; j < 8; j++)
            r[j] = __ldcs(xs + (size_t)__ldcs(srt + e + j) * (DIM / 4) + qoff);
        #pragma unroll
        for (int j = 0; j < 8; j++) addv(r[j]);
    }
    for (; e + 1 < end; e += 2) {
        uint2 r0 = __ldcs(xs + (size_t)__ldcs(srt + e) * (DIM / 4) + qoff);
        uint2 r1 = __ldcs(xs + (size_t)__ldcs(srt + e + 1) * (DIM / 4) + qoff);
        addv(r0); addv(r1);
    }
    if (e < end) {
        uint2 r = __ldcs(xs + (size_t)__ldcs(srt + e) * (DIM / 4) + qoff);
        addv(r);
    }
    int d = end - beg;
    float inv = 1.0f / (float)(d > 1 ? d : 1);
    __half2 lo = __floats2half2_rn(acc.x * inv, acc.y * inv);
    __half2 hi = __floats2half2_rn(acc.z * inv, acc.w * inv);
    uint2 o;
    o.x = *reinterpret_cast<uint32_t*>(&lo);
    o.y = *reinterpret_cast<uint32_t*>(&hi);
    __stcs(reinterpret_cast<uint2*>(aggout) + (size_t)v * (DIM / 4) + qoff, o);
}

// W[k][n] fp32 -> Wt[n][k] fp16; batched over 3 weights via blockIdx.z
__global__ void transpose_round_all_kernel(const float* __restrict__ W0,
                                           const float* __restrict__ W1,
                                           const float* __restrict__ W2) {
    int rel = blockIdx.z;
    const float* W = (rel == 0) ? W0 : (rel == 1) ? W1 : W2;
    __half* Wt = (rel == 0) ? g_wt0 : (rel == 1) ? g_wt1 : g_wt2;
    __shared__ float tile[32][33];
    int bx = blockIdx.x * 32, by = blockIdx.y * 32;
    int tx = threadIdx.x, ty = threadIdx.y;   // 32 x 8
    #pragma unroll
    for (int i = 0; i < 32; i += 8)
        tile[ty + i][tx] = W[(size_t)(by + ty + i) * DIM + bx + tx];
    __syncthreads();
    #pragma unroll
    for (int i = 0; i < 32; i += 8)
        Wt[(size_t)(bx + ty + i) * DIM + by + tx] = __float2half_rn(tile[tx][ty + i]);
}

// ---------------- cp.async + ldmatrix FP16 GEMM, BM=256 x BN=128, BK=64 ----------------
// BK = 64 halfs = 128B row = one SW128 atom. Chunk swizzle: c' = c ^ (row & 7).
// Per stage: A-half0 16KB + A-half1 16KB + B 16KB = 48KB; 3-stage = 144KB.
#define TILE_BYTES   16384
#define STAGE_BYTES  (3 * TILE_BYTES)
#define NSTAGE 3
#define GEMM_SMEM_DYN (NSTAGE * STAGE_BYTES)   // 147456 B

template <int CHUNKS>
__device__ __forceinline__ void gemm_body(
    int bm, int bn,
    const __half* __restrict__ A0, const __half* __restrict__ A1,
    const __half* __restrict__ Wt0, const __half* __restrict__ Wt1,
    const float* __restrict__ bias0, const float* __restrict__ bias1,
    float* __restrict__ C, int M, float* smem)
{
    const uint32_t smem_u32 = smem_to_u32(smem);

    const int t      = threadIdx.x;
    const int lane   = t & 31;
    const int warp   = t >> 5;
    const int warp_m = warp >> 2;   // 0..1 (within each 128-row half)
    const int warp_n = warp & 3;    // 0..3
    const int g      = lane >> 2;
    const int tid4   = lane & 3;
    const int lane7  = lane & 7;

    const int KT = 16 * CHUNKS;   // BK=64 tiles per K=1024

    const int s_row = t >> 3;     // + it*32
    const int s_c   = t & 7;      // 16B chunk within 128B row (8 halfs)

    auto stage = [&](int kt, int buf) {
        const __half* Asrc = (CHUNKS == 2 && kt >= 16) ? A1 : A0;
        const __half* Wsrc = (CHUNKS == 2 && kt >= 16) ? Wt1 : Wt0;
        const int k0 = (kt & 15) * 64;                 // half offset
        const uint32_t base = smem_u32 + (uint32_t)buf * STAGE_BYTES;
        #pragma unroll
        for (int it = 0; it < 4; ++it) {
            int row = s_row + it * 32;                 // 0..127
            uint32_t dst = (uint32_t)(row * 128 + ((s_c ^ (row & 7)) * 16));
            // A half 0
            int gm0 = bm + row;
            int gm0c = (gm0 < M) ? gm0 : 0;
            cp_async16(base + dst, Asrc + (size_t)gm0c * DIM + k0 + s_c * 8,
                       (gm0 < M) ? 16u : 0u);
            // A half 1
            int gm1 = bm + 128 + row;
            int gm1c = (gm1 < M) ? gm1 : 0;
            cp_async16(base + TILE_BYTES + dst, Asrc + (size_t)gm1c * DIM + k0 + s_c * 8,
                       (gm1 < M) ? 16u : 0u);
            // B
            int gn = bn + row;
            cp_async16(base + 2 * TILE_BYTES + dst, Wsrc + (size_t)gn * DIM + k0 + s_c * 8, 16u);
        }
    };

    // ldmatrix address components (loop-invariant); identical formulas to the
    // validated tf32 kernel: a 16B chunk is one k-segment either way.
    uint32_t rowoff_a[4], rowoff_bp[2], cka[4], ckb[4];
    {
        int khia = lane >> 4;          // A x4: k-seg half select
        int khib = (lane >> 3) & 1;    // B x4: k-seg half select
        int ntp  = lane >> 4;          // B x4: n-subtile within pair
        #pragma unroll
        for (int mt = 0; mt < 4; mt++)
            rowoff_a[mt] = (uint32_t)((warp_m * 64 + mt * 16 + (lane & 15)) * 128);
        #pragma unroll
        for (int p = 0; p < 2; p++)
            rowoff_bp[p] = (uint32_t)((warp_n * 32 + (p * 2 + ntp) * 8 + lane7) * 128);
        #pragma unroll
        for (int k = 0; k < 4; k++) {
            cka[k] = (uint32_t)((((2 * k + khia) ^ lane7)) * 16);
            ckb[k] = (uint32_t)((((2 * k + khib) ^ lane7)) * 16);
        }
    }

    float c[2][4][4][4];
    #pragma unroll
    for (int h = 0; h < 2; h++)
        #pragma unroll
        for (int mt = 0; mt < 4; mt++)
            #pragma unroll
            for (int nt = 0; nt < 4; nt++)
                #pragma unroll
                for (int r = 0; r < 4; r++) c[h][mt][nt][r] = 0.f;

    auto compute = [&](int buf) {
        const uint32_t base = smem_u32 + (uint32_t)buf * STAGE_BYTES;
        const uint32_t bbase = base + 2 * TILE_BYTES;
        #pragma unroll
        for (int kstep = 0; kstep < 4; ++kstep) {     // 4 x k16 = BK 64
            uint32_t b[4][2];
            #pragma unroll
            for (int p = 0; p < 2; p++) {
                uint32_t bq[4];
                ldsm_x4(bq, bbase + rowoff_bp[p] + ckb[kstep]);
                b[2 * p][0] = bq[0]; b[2 * p][1] = bq[1];
                b[2 * p + 1][0] = bq[2]; b[2 * p + 1][1] = bq[3];
            }
            #pragma unroll
            for (int h = 0; h < 2; h++) {
                const uint32_t abase = base + (uint32_t)h * TILE_BYTES;
                #pragma unroll
                for (int mt = 0; mt < 4; mt++) {
                    uint32_t a[4];
                    ldsm_x4(a, abase + rowoff_a[mt] + cka[kstep]);
                    #pragma unroll
                    for (int nt = 0; nt < 4; nt++)
                        mma_f16(c[h][mt][nt][0], c[h][mt][nt][1],
                                c[h][mt][nt][2], c[h][mt][nt][3],
                                a[0], a[1], a[2], a[3],
                                b[nt][0], b[nt][1]);
                }
            }
        }
    };

    stage(0, 0); cp_async_commit();
    stage(1, 1); cp_async_commit();

    int buf = 0;
    for (int kt = 0; kt < KT; ++kt) {
        cp_async_wait<1>();
        __syncthreads();
        compute(buf);
        if (kt + 2 < KT) stage(kt + 2, (buf + 2) % NSTAGE);
        cp_async_commit();
        buf = (buf + 1) % NSTAGE;
    }

    // C stores evict-first (dead stream)
    #pragma unroll
    for (int h = 0; h < 2; h++) {
        #pragma unroll
        for (int mt = 0; mt < 4; mt++) {
            int r0 = bm + h * 128 + warp_m * 64 + mt * 16 + g;
            int r1 = r0 + 8;
            #pragma unroll
            for (int nt = 0; nt < 4; nt++) {
                int col = bn + warp_n * 32 + nt * 8 + tid4 * 2;
                float bv0 = bias0[col], bv1 = bias0[col + 1];
                if (CHUNKS == 2) { bv0 += bias1[col]; bv1 += bias1[col + 1]; }
                if (r0 < M) {
                    float* p = &C[(size_t)r0 * DIM + col];
                    __stcs(reinterpret_cast<float2*>(p),
                           make_float2(c[h][mt][nt][0] + bv0, c[h][mt][nt][1] + bv1));
                }
                if (r1 < M) {
                    float* p = &C[(size_t)r1 * DIM + col];
                    __stcs(reinterpret_cast<float2*>(p),
                           make_float2(c[h][mt][nt][2] + bv0, c[h][mt][nt][3] + bv1));
                }
            }
        }
    }
}

// combined GEMM launch: blocks [0, GEMM_BLOCKS) = prot (K=2048, dpi+ppi);
// blocks [GEMM_BLOCKS, 2*GEMM_BLOCKS) = ddi (K=1024).
__global__ __launch_bounds__(256) void gemm_combined_kernel(
    const float* __restrict__ bias_dpi, const float* __restrict__ bias_ppi,
    const float* __restrict__ bias_ddi,
    float* __restrict__ Cprot, float* __restrict__ Cdrug, int M)
{
    extern __shared__ float smem[];
    if (blockIdx.x < GEMM_BLOCKS) {
        int bm = (blockIdx.x / GEMM_NBLKS) * 256;
        int bn = (blockIdx.x % GEMM_NBLKS) * 128;
        gemm_body<2>(bm, bn, g_agg0, g_agg1, g_wt0, g_wt1,
                     bias_dpi, bias_ppi, Cprot, M, smem);
    } else {
        int b = blockIdx.x - GEMM_BLOCKS;
        int bm = (b / GEMM_NBLKS) * 256;
        int bn = (b % GEMM_NBLKS) * 128;
        gemm_body<1>(bm, bn, g_agg2, nullptr, g_wt2, nullptr,
                     bias_ddi, nullptr, Cdrug, M, smem);
    }
}

// ---------------- launch (single capture stream) ----------------
extern "C" void kernel_launch(void* const* d_in, const int* in_sizes, int n_in,
                              void* d_out, int out_size)
{
    const float* x_drug = (const float*)d_in[0];
    const float* x_prot = (const float*)d_in[1];
    const float* W_ddi  = (const float*)d_in[2];
    const float* b_ddi  = (const float*)d_in[3];
    const float* W_dpi  = (const float*)d_in[4];
    const float* b_dpi  = (const float*)d_in[5];
    const float* W_ppi  = (const float*)d_in[6];
    const float* b_ppi  = (const float*)d_in[7];
    const int* src_ddi  = (const int*)d_in[8];
    const int* dst_ddi  = (const int*)d_in[9];
    const int* src_dpi  = (const int*)d_in[10];
    const int* dst_dpi  = (const int*)d_in[11];
    const int* src_ppi  = (const int*)d_in[12];
    const int* dst_ppi  = (const int*)d_in[13];

    float* out_drug = (float*)d_out;
    float* out_prot = out_drug + (size_t)N_NODE * DIM;

    __half* xhd; cudaGetSymbolAddress((void**)&xhd, g_xh_drug);
    __half* xhp; cudaGetSymbolAddress((void**)&xhp, g_xh_prot);

    cudaFuncSetAttribute(gemm_combined_kernel,
                         cudaFuncAttributeMaxDynamicSharedMemorySize, GEMM_SMEM_DYN);

    // ---- fp32 -> fp16 input conversion (both node tables) ----
    {
        dim3 g(((N_NODE * (DIM / 4)) + 255) / 256, 2);
        convert_x_kernel<<<g, 256>>>(
            reinterpret_cast<const float4*>(x_drug), reinterpret_cast<const float4*>(x_prot),
            reinterpret_cast<uint2*>(xhd), reinterpret_cast<uint2*>(xhp));
    }

    // ---- batched sorts: rel 0 = dpi, 1 = ppi, 2 = ddi ----
    zero_deg_all_kernel<<<(3 * N_NODE + 255) / 256, 256>>>();
    {
        dim3 g((N_EDGE + 255) / 256, 3);
        hist_all_kernel<<<g, 256>>>(dst_dpi, dst_ppi, dst_ddi);
    }
    {
        dim3 g(NBLK_SCAN, 3);
        scan_block_all_kernel<<<g, 1024>>>();
        scan_add_all_kernel<<<g, 1024>>>();
    }
    {
        dim3 g((N_EDGE + 255) / 256, 3);
        scatter_all_kernel<<<g, 256>>>(src_dpi, dst_dpi, src_ppi, dst_ppi, src_ddi, dst_ddi);
    }

    // ---- batched weight transposes (fp32 -> fp16 transposed) ----
    {
        dim3 g(32, 32, 3), b(32, 8);
        transpose_round_all_kernel<<<g, b>>>(W_dpi, W_ppi, W_ddi);
    }

    // ---- merged fp16 aggregate launch (all 6 passes) ----
    aggregate_all_kernel<<<6 * N_NODE, 128>>>();

    // ---- single combined fp16 GEMM launch: prot (K=2048) + ddi (K=1024) ----
    gemm_combined_kernel<<<2 * GEMM_BLOCKS, 256, GEMM_SMEM_DYN>>>(
        b_dpi, b_ppi, b_ddi, out_prot, out_drug, N_NODE);
}